// round 2
// baseline (speedup 1.0000x reference)
#include <cuda_runtime.h>
#include <math.h>

// ---------------- static configuration ----------------
#define Bn     32
#define Tn     4096
#define Cn     3
#define NSC    128
#define NPSI   4096
#define PADL   2047
#define LP     8190           // Tn + 2*PADL
#define DXSTR  8192
#define NROW   96             // Cn * Bn
#define KSTR   3328           // >= max kernel length 3265, mult of 4
#define KSTR2  (2*KSTR)
#define NP12MAX 3276          // max n padded to multiple of 12
#define OUTH   224
#define OUTW   224
#define TT     1024           // conv outputs per block
#define NTHR   128
#define OUTN   (Bn*OUTH*OUTW*Cn)

typedef unsigned long long ull;

// ---------------- device scratch ----------------
__device__ float  g_dx[NROW * DXSTR];                       // 3 MB
__device__ float  g_kern2[NSC * KSTR2];                     // 3.4 MB (pair-duplicated)
__device__ float  g_coef[(size_t)NSC * NROW * Tn];          // 192 MB
__device__ float  g_tmpA[NSC * NROW * OUTW];                // 11 MB
__device__ int    g_n[NSC];
__device__ int    g_d0[NSC];
__device__ float  g_nsq[NSC];
__device__ double g_sden[NSC];
__device__ float  g_wt[OUTW * 40];
__device__ int    g_wst[OUTW];
__device__ int    g_wcnt[OUTW];
__device__ int    g_whi[OUTH * 2];
__device__ float  g_whw[OUTH * 2];

// ---------------- f32x2 helpers ----------------
__device__ __forceinline__ ull pk(float lo, float hi) {
    ull r; asm("mov.b64 %0, {%1, %2};" : "=l"(r) : "f"(lo), "f"(hi)); return r;
}
__device__ __forceinline__ float2 upk(ull v) {
    float2 r; asm("mov.b64 {%0, %1}, %2;" : "=f"(r.x), "=f"(r.y) : "l"(v)); return r;
}
__device__ __forceinline__ void fma2(ull& d, ull a, ull b) {
    asm("fma.rn.f32x2 %0, %1, %2, %0;" : "+l"(d) : "l"(a), "l"(b));
}

// ---------------- setup ----------------
__global__ void k_setup() {
    int tid = threadIdx.x;
    if (tid < NSC) {
        double l2 = log10(2.0), lM = log10(204.0);
        double y = (tid == NSC - 1) ? lM : (l2 + (double)tid * ((lM - l2) / (double)(NSC - 1)));
        float  sf = (float)pow(10.0, y);
        double sd = (double)sf;
        int n = (int)ceil(sd * 16.0 + 1.0);
        int d0 = (4094 - n) / 2; if (d0 < 0) d0 = 0;
        g_n[tid]   = n;
        g_d0[tid]  = d0;
        g_nsq[tid] = -sqrtf(sf);
        g_sden[tid] = sd * (16.0 / 4095.0);
    }
    if (tid < OUTW) {
        double inv = 4096.0 / 224.0;
        double ks  = inv;
        double sf  = ((double)tid + 0.5) * inv - 0.5;
        int lo = (int)ceil(sf - ks);  if (lo < 0) lo = 0;
        int hi = (int)floor(sf + ks); if (hi > Tn - 1) hi = Tn - 1;
        double tot = 0.0;
        for (int i = lo; i <= hi; i++) {
            double w = 1.0 - fabs((double)i - sf) / ks; if (w < 0.0) w = 0.0;
            tot += w;
        }
        int cnt = hi - lo + 1;
        g_wst[tid] = lo; g_wcnt[tid] = cnt;
        for (int j = 0; j < cnt; j++) {
            double w = 1.0 - fabs((double)(lo + j) - sf) / ks; if (w < 0.0) w = 0.0;
            g_wt[tid * 40 + j] = (float)(w / tot);
        }
    }
    if (tid < OUTH) {
        double inv = 128.0 / 224.0;
        double sf  = ((double)tid + 0.5) * inv - 0.5;
        int ia = (int)floor(sf);
        int i0 = ia, i1 = ia + 1;
        double w0 = 1.0 - (sf - (double)ia);
        double w1 = sf - (double)ia;
        bool v0 = (i0 >= 0 && i0 < NSC);
        bool v1 = (i1 >= 0 && i1 < NSC);
        double tot = (v0 ? w0 : 0.0) + (v1 ? w1 : 0.0);
        int   o0 = v0 ? i0 : (v1 ? i1 : 0);
        int   o1 = v1 ? i1 : (v0 ? i0 : 0);
        float f0 = v0 ? (float)(w0 / tot) : 0.0f;
        float f1 = v1 ? (float)(w1 / tot) : 0.0f;
        if (!v0 && v1) { f0 = (float)(w1 / tot); f1 = 0.0f; }
        g_whi[tid * 2 + 0] = o0; g_whi[tid * 2 + 1] = o1;
        g_whw[tid * 2 + 0] = f0; g_whw[tid * 2 + 1] = f1;
    }
}

// ---------------- build flipped gathered kernels (pair-duplicated) ----------------
__global__ void k_buildkern(const float* __restrict__ psi) {
    int sc = blockIdx.x;
    int n = g_n[sc];
    double den = g_sden[sc];
    for (int k = threadIdx.x; k < KSTR; k += blockDim.x) {
        float v = 0.0f;
        if (k < n) {
            int m = n - 1 - k;                              // flip
            int j = (int)floor((double)m / den);
            if (j < 0) j = 0;
            if (j > NPSI - 1) j = NPSI - 1;
            v = psi[j];
        }
        g_kern2[sc * KSTR2 + 2 * k]     = v;
        g_kern2[sc * KSTR2 + 2 * k + 1] = v;
    }
}

// ---------------- dx = diff(reflect_pad(x)) ----------------
__device__ __forceinline__ float xp_val(const float* __restrict__ x, int b, int c, int p) {
    int i = p - PADL;
    if (i < 0) i = -i;
    else if (i >= Tn) i = 2 * (Tn - 1) - i;
    return x[((size_t)b * Tn + i) * Cn + c];
}

__global__ void k_dx(const float* __restrict__ x) {
    int idx = blockIdx.x * blockDim.x + threadIdx.x;
    if (idx >= NROW * DXSTR) return;
    int r = idx >> 13;
    int p = idx & (DXSTR - 1);
    int c = r / Bn, b = r % Bn;
    float v = 0.0f;
    if (p <= LP - 2) v = xp_val(x, b, c, p + 1) - xp_val(x, b, c, p);
    g_dx[idx] = v;
}

// ---------------- main convolution (f32x2 packed) ----------------
// coef[sc,row,t] = -sqrt(s) * sum_k dx[row, d0+t+k] * kern[sc,k]
#define FMAS(pA,pB,pC,pD, klo) \
    fma2(a0, pA, klo); fma2(a1, pB, klo); fma2(a2, pC, klo); fma2(a3, pD, klo);

__global__ __launch_bounds__(NTHR) void k_conv() {
    __shared__ __align__(16) float sx[TT + NP12MAX + 16];
    __shared__ __align__(16) float sk[2 * NP12MAX + 8];

    int sc  = blockIdx.z;
    int row = blockIdx.y;
    int t0  = blockIdx.x * TT;
    int n   = g_n[sc];
    int np12 = ((n + 11) / 12) * 12;
    int d0  = g_d0[sc];
    float nsq = g_nsq[sc];

    const float* gx = g_dx + row * DXSTR + d0 + t0;
    const float* gk = g_kern2 + sc * KSTR2;

    int xlen = TT + np12 + 16;
    for (int i = threadIdx.x; i < xlen; i += NTHR) sx[i] = gx[i];
    int klen = 2 * np12 + 8;                       // multiple of 4
    for (int i = threadIdx.x * 4; i < klen; i += NTHR * 4)
        *(float4*)(sk + i) = *(const float4*)(gk + i);
    __syncthreads();

    const float* xs = sx + threadIdx.x * 8;

    // prologue: window w0..w11 for q=0
    float4 A0 = *(const float4*)(xs);
    float4 A1 = *(const float4*)(xs + 4);
    float4 A2 = *(const float4*)(xs + 8);
    ull P0 = pk(A0.x, A0.y), P2 = pk(A0.z, A0.w);
    ull P4 = pk(A1.x, A1.y), P6 = pk(A1.z, A1.w);
    ull S1 = pk(A0.y, A0.z), S3 = pk(A0.w, A1.x), S5 = pk(A1.y, A1.z);
    float cw = A1.w;
    const ulonglong2* kp = (const ulonglong2*)sk;
    ulonglong2 Ka = kp[0], Kb = kp[1];
    kp += 2;
    const float* xp = xs + 12;

    ull a0 = 0ULL, a1 = 0ULL, a2 = 0ULL, a3 = 0ULL;

    int nb = np12 / 12;
    for (int b = 0; b < nb; b++) {
        // ======== q = 3b ========
        float4 N0 = *(const float4*)(xp);
        ulonglong2 Kc = kp[0], Kd = kp[1];
        ull S7  = pk(cw,   A2.x), S9  = pk(A2.y, A2.z);
        ull P8  = pk(A2.x, A2.y), P6n = pk(A2.z, A2.w);
        FMAS(P0, P2, P4, P6,  Ka.x)
        FMAS(S1, S3, S5, S7,  Ka.y)
        FMAS(P2, P4, P6, P8,  Kb.x)
        FMAS(S3, S5, S7, S9,  Kb.y)
        // ======== q = 3b+1 ========
        float4 N1 = *(const float4*)(xp + 4);
        ulonglong2 Ke = kp[2], Kf = kp[3];
        ull S7b  = pk(A2.w, N0.x), S9b  = pk(N0.y, N0.z);
        ull P8b  = pk(N0.x, N0.y), P6nb = pk(N0.z, N0.w);
        FMAS(P4, P6, P8,  P6n,  Kc.x)
        FMAS(S5, S7, S9,  S7b,  Kc.y)
        FMAS(P6, P8, P6n, P8b,  Kd.x)
        FMAS(S7, S9, S7b, S9b,  Kd.y)
        // ======== q = 3b+2 ========
        float4 N2 = *(const float4*)(xp + 8);
        ulonglong2 Kg = kp[4], Kh = kp[5];
        ull S7c  = pk(N0.w, N1.x), S9c  = pk(N1.y, N1.z);
        ull P8c  = pk(N1.x, N1.y), P6nc = pk(N1.z, N1.w);
        FMAS(P8,  P6n, P8b,  P6nb, Ke.x)
        FMAS(S9,  S7b, S9b,  S7c,  Ke.y)
        FMAS(P6n, P8b, P6nb, P8c,  Kf.x)
        FMAS(S7b, S9b, S7c,  S9c,  Kf.y)
        // ======== rotate state for next loop ========
        P0 = P8b; P2 = P6nb; P4 = P8c; P6 = P6nc;
        S1 = S9b; S3 = S7c;  S5 = S9c;
        cw = N1.w; A2 = N2;
        Ka = Kg; Kb = Kh;
        kp += 6; xp += 12;
    }

    float2 r0 = upk(a0), r1 = upk(a1), r2 = upk(a2), r3 = upk(a3);
    float* dst = g_coef + ((size_t)(sc * NROW + row)) * Tn + t0 + threadIdx.x * 8;
    float4 v0 = make_float4(nsq * r0.x, nsq * r0.y, nsq * r1.x, nsq * r1.y);
    float4 v1 = make_float4(nsq * r2.x, nsq * r2.y, nsq * r3.x, nsq * r3.y);
    *(float4*)(dst)     = v0;
    *(float4*)(dst + 4) = v1;
}

// ---------------- resize stage A: t axis 4096 -> 224 ----------------
__global__ void k_resize_t() {
    __shared__ __align__(16) float srow[Tn];
    int sr = blockIdx.x;                                    // sc*96 + row
    const float* src = g_coef + (size_t)sr * Tn;
    for (int i = threadIdx.x * 4; i < Tn; i += blockDim.x * 4)
        *(float4*)(srow + i) = *(const float4*)(src + i);
    __syncthreads();
    for (int w = threadIdx.x; w < OUTW; w += blockDim.x) {
        int st = g_wst[w], cnt = g_wcnt[w];
        const float* wt = g_wt + w * 40;
        float acc = 0.0f;
        for (int j = 0; j < cnt; j++) acc += wt[j] * srow[st + j];
        g_tmpA[sr * OUTW + w] = acc;
    }
}

// ---------------- resize stage B: scale axis 128 -> 224 ----------------
__global__ void k_resize_h(float* __restrict__ out) {
    int idx = blockIdx.x * blockDim.x + threadIdx.x;
    if (idx >= OUTN) return;
    int c = idx % Cn;
    int w = (idx / Cn) % OUTW;
    int h = (idx / (Cn * OUTW)) % OUTH;
    int b = idx / (Cn * OUTW * OUTH);
    int i0 = g_whi[h * 2 + 0], i1 = g_whi[h * 2 + 1];
    float f0 = g_whw[h * 2 + 0], f1 = g_whw[h * 2 + 1];
    int rb = (c * Bn + b) * OUTW + w;
    out[idx] = f0 * g_tmpA[i0 * NROW * OUTW + rb] + f1 * g_tmpA[i1 * NROW * OUTW + rb];
}

// ---------------- launch ----------------
extern "C" void kernel_launch(void* const* d_in, const int* in_sizes, int n_in,
                              void* d_out, int out_size) {
    const float* x   = (const float*)d_in[0];       // (32, 4096, 3) f32
    const float* psi = (const float*)d_in[1];       // (4096,) f32
    float* out = (float*)d_out;

    k_setup<<<1, 256>>>();
    k_buildkern<<<NSC, 256>>>(psi);
    int dxtot = NROW * DXSTR;
    k_dx<<<(dxtot + 255) / 256, 256>>>(x);
    k_conv<<<dim3(Tn / TT, NROW, NSC), NTHR>>>();
    k_resize_t<<<NSC * NROW, 256>>>();
    k_resize_h<<<(OUTN + 255) / 256, 256>>>(out);
}

// round 3
// speedup vs baseline: 1.3399x; 1.3399x over previous
#include <cuda_runtime.h>
#include <math.h>

// ---------------- static configuration ----------------
#define Bn     32
#define Tn     4096
#define Cn     3
#define NSC    128
#define NPSI   4096
#define PADL   2047
#define LP     8190           // Tn + 2*PADL
#define DXSTR  8192
#define NROW   96             // Cn * Bn
#define KSTR   3328           // >= max kernel length 3265
#define OUTH   224
#define OUTW   224
#define OUTN   (Bn*OUTH*OUTW*Cn)

#define EKSTR  3584           // E row stride (mult of 512 chunk)
#define CH     512            // E chunk length in apply
#define SESTR  520            // sE per-class stride (bank stagger)
#define SDXW   7440           // dx window per row in smem
#define SDXP   7444           // dx row stride (bank stagger)
#define ATHR   224            // apply threads = one per w

// ---------------- device scratch ----------------
__device__ float  g_dx[NROW * DXSTR];                       // 3 MB
__device__ float  g_kern[NSC * KSTR];                       // 1.7 MB
__device__ float  g_ek[(size_t)NSC * 9 * EKSTR];            // 16.5 MB effective kernels
__device__ float  g_tmpA[NSC * NROW * OUTW];                // 11 MB
__device__ int    g_n[NSC];
__device__ int    g_d0[NSC];
__device__ int    g_lp[NSC];
__device__ float  g_nsq[NSC];
__device__ double g_sden[NSC];
__device__ float  g_wt[OUTW * 40];
__device__ int    g_wst[OUTW];
__device__ int    g_wcnt[OUTW];
__device__ int    g_whi[OUTH * 2];
__device__ float  g_whw[OUTH * 2];

// ---------------- setup: scales, crop offsets, resize weights ----------------
__global__ void k_setup() {
    int tid = threadIdx.x;

    if (tid < NSC) {
        double l2 = log10(2.0), lM = log10(204.0);
        double y = (tid == NSC - 1) ? lM : (l2 + (double)tid * ((lM - l2) / (double)(NSC - 1)));
        float  sf = (float)pow(10.0, y);
        double sd = (double)sf;
        int n = (int)ceil(sd * 16.0 + 1.0);
        int d0 = (4094 - n) / 2; if (d0 < 0) d0 = 0;
        g_n[tid]   = n;
        g_d0[tid]  = d0;
        g_lp[tid]  = (n + 40 + 15) & ~15;
        g_nsq[tid] = -sqrtf(sf);
        g_sden[tid] = sd * (16.0 / 4095.0);
    }
    if (tid < OUTW) {
        double inv = 4096.0 / 224.0;
        double ks  = inv;
        double sf  = ((double)tid + 0.5) * inv - 0.5;
        int lo = (int)ceil(sf - ks);  if (lo < 0) lo = 0;
        int hi = (int)floor(sf + ks); if (hi > Tn - 1) hi = Tn - 1;
        double tot = 0.0;
        for (int i = lo; i <= hi; i++) {
            double w = 1.0 - fabs((double)i - sf) / ks; if (w < 0.0) w = 0.0;
            tot += w;
        }
        int cnt = hi - lo + 1;
        g_wst[tid] = lo; g_wcnt[tid] = cnt;
        for (int j = 0; j < cnt; j++) {
            double w = 1.0 - fabs((double)(lo + j) - sf) / ks; if (w < 0.0) w = 0.0;
            g_wt[tid * 40 + j] = (float)(w / tot);
        }
        for (int j = cnt; j < 40; j++) g_wt[tid * 40 + j] = 0.0f;
    }
    if (tid < OUTH) {
        double inv = 128.0 / 224.0;
        double sf  = ((double)tid + 0.5) * inv - 0.5;
        int ia = (int)floor(sf);
        int i0 = ia, i1 = ia + 1;
        double w0 = 1.0 - (sf - (double)ia);
        double w1 = sf - (double)ia;
        bool v0 = (i0 >= 0 && i0 < NSC);
        bool v1 = (i1 >= 0 && i1 < NSC);
        double tot = (v0 ? w0 : 0.0) + (v1 ? w1 : 0.0);
        int   o0 = v0 ? i0 : (v1 ? i1 : 0);
        int   o1 = v1 ? i1 : (v0 ? i0 : 0);
        float f0 = v0 ? (float)(w0 / tot) : 0.0f;
        float f1 = v1 ? (float)(w1 / tot) : 0.0f;
        if (!v0 && v1) { f0 = (float)(w1 / tot); f1 = 0.0f; }
        g_whi[tid * 2 + 0] = o0; g_whi[tid * 2 + 1] = o1;
        g_whw[tid * 2 + 0] = f0; g_whw[tid * 2 + 1] = f1;
    }
}

// ---------------- build flipped gathered wavelet kernels ----------------
__global__ void k_buildkern(const float* __restrict__ psi) {
    int sc = blockIdx.x;
    int n = g_n[sc];
    double den = g_sden[sc];
    for (int k = threadIdx.x; k < KSTR; k += blockDim.x) {
        float v = 0.0f;
        if (k < n) {
            int m = n - 1 - k;                              // flip
            int j = (int)floor((double)m / den);
            if (j < 0) j = 0;
            if (j > NPSI - 1) j = NPSI - 1;
            v = psi[j];
        }
        g_kern[sc * KSTR + k] = v;
    }
}

// ---------------- dx = diff(reflect_pad(x)) ----------------
__device__ __forceinline__ float xp_val(const float* __restrict__ x, int b, int c, int p) {
    int i = p - PADL;
    if (i < 0) i = -i;
    else if (i >= Tn) i = 2 * (Tn - 1) - i;
    return x[((size_t)b * Tn + i) * Cn + c];
}

__global__ void k_dx(const float* __restrict__ x) {
    int idx = blockIdx.x * blockDim.x + threadIdx.x;
    if (idx >= NROW * DXSTR) return;
    int r = idx >> 13;
    int p = idx & (DXSTR - 1);
    int c = r / Bn, b = r % Bn;
    float v = 0.0f;
    if (p <= LP - 2) v = xp_val(x, b, c, p + 1) - xp_val(x, b, c, p);
    g_dx[idx] = v;
}

// ---------------- build effective (resize-folded) kernels ----------------
// E[s,cls,p] = nsq_s * sum_k kern_s[k] * wt[wrep, p - sh - k], zero-padded.
// cls 0..6 -> representatives w=7..13 (interior, unclipped, period-7 exact);
// cls 7 -> w=0 (left-clipped); cls 8 -> w=223 (right-clipped).
__global__ void k_ebuild() {
    __shared__ float skern[KSTR];
    __shared__ float swt[40];
    int c = blockIdx.x;         // class 0..8
    int s = blockIdx.y;
    int n = g_n[s], d0 = g_d0[s];
    float nsq = g_nsq[s];
    int wrep = (c < 7) ? (7 + c) : ((c == 7) ? 0 : 223);
    int st = g_wst[wrep], cnt = g_wcnt[wrep];
    int sh = (d0 + st) & 3;
    for (int i = threadIdx.x; i < n; i += blockDim.x) skern[i] = g_kern[s * KSTR + i];
    if (threadIdx.x < 40) swt[threadIdx.x] = g_wt[wrep * 40 + threadIdx.x];
    __syncthreads();
    int Len = n + cnt - 1;
    float* dst = g_ek + ((size_t)(s * 9 + c)) * EKSTR;
    for (int p = threadIdx.x; p < EKSTR; p += blockDim.x) {
        int pp = p - sh;
        float acc = 0.0f;
        if (pp >= 0 && pp < Len) {
            int k0 = pp - cnt + 1; if (k0 < 0) k0 = 0;
            int k1 = pp; if (k1 > n - 1) k1 = n - 1;
            for (int k = k0; k <= k1; k++) acc += skern[k] * swt[pp - k];
            acc *= nsq;
        }
        dst[p] = acc;
    }
}

// ---------------- main apply: tmpA[s,row,w] = dot(dx window, E row) ----------------
extern __shared__ float sm[];
__global__ __launch_bounds__(ATHR) void k_apply() {
    int s  = blockIdx.y;
    int rp = blockIdx.x;                 // row pair
    int tid = threadIdx.x;               // = w (0..223)
    int d0 = g_d0[s], lp = g_lp[s];
    int base = (d0 & ~3) - 4;            // 4-aligned, >= 410

    float* sdx = sm;                     // 2 rows x SDXP
    float* sE  = sm + 2 * SDXP;          // 9 classes x SESTR

    int wlen = 4100 + lp; if (wlen > SDXW) wlen = SDXW;
    int row0 = rp * 2;
    {
        const float* s0 = g_dx + (size_t)row0 * DXSTR + base;
        const float* s1 = s0 + DXSTR;
        for (int i = tid * 4; i < wlen; i += ATHR * 4) {
            *(float4*)(sdx + i)        = *(const float4*)(s0 + i);
            *(float4*)(sdx + SDXP + i) = *(const float4*)(s1 + i);
        }
    }

    int w = tid;
    int cls = (w == 0) ? 7 : ((w == 223) ? 8 : (w % 7));
    int st  = g_wst[w];
    int ofs = ((d0 + st) & ~3) - base;   // >= 4, multiple of 4
    const float* eS = sE + cls * SESTR;

    float acc0 = 0.0f, acc1 = 0.0f;
    int nch = (lp + CH - 1) / CH;
    const float* ekbase = g_ek + ((size_t)(s * 9)) * EKSTR;

    for (int ch = 0; ch < nch; ch++) {
        int pc = ch * CH;
        __syncthreads();
        for (int idx = tid; idx < 9 * (CH / 4); idx += ATHR) {
            int c  = idx / (CH / 4);
            int i4 = idx - c * (CH / 4);
            *(float4*)(sE + c * SESTR + 4 * i4) =
                *(const float4*)(ekbase + (size_t)c * EKSTR + pc + 4 * i4);
        }
        __syncthreads();
        int qn = lp - pc; if (qn > CH) qn = CH; qn >>= 2;
        const float* xa = sdx + ofs + pc;
        const float* xb = xa + SDXP;
        #pragma unroll 4
        for (int q = 0; q < qn; q++) {
            float4 e = *(const float4*)(eS + 4 * q);
            float4 a = *(const float4*)(xa + 4 * q);
            float4 b = *(const float4*)(xb + 4 * q);
            acc0 = fmaf(a.x, e.x, fmaf(a.y, e.y, fmaf(a.z, e.z, fmaf(a.w, e.w, acc0))));
            acc1 = fmaf(b.x, e.x, fmaf(b.y, e.y, fmaf(b.z, e.z, fmaf(b.w, e.w, acc1))));
        }
    }

    g_tmpA[(s * NROW + row0)     * OUTW + w] = acc0;
    g_tmpA[(s * NROW + row0 + 1) * OUTW + w] = acc1;
}

// ---------------- resize stage B: scale axis 128 -> 224 ----------------
__global__ void k_resize_h(float* __restrict__ out) {
    int idx = blockIdx.x * blockDim.x + threadIdx.x;
    if (idx >= OUTN) return;
    int c = idx % Cn;
    int w = (idx / Cn) % OUTW;
    int h = (idx / (Cn * OUTW)) % OUTH;
    int b = idx / (Cn * OUTW * OUTH);
    int i0 = g_whi[h * 2 + 0], i1 = g_whi[h * 2 + 1];
    float f0 = g_whw[h * 2 + 0], f1 = g_whw[h * 2 + 1];
    int rb = (c * Bn + b) * OUTW + w;
    out[idx] = f0 * g_tmpA[i0 * NROW * OUTW + rb] + f1 * g_tmpA[i1 * NROW * OUTW + rb];
}

// ---------------- launch ----------------
extern "C" void kernel_launch(void* const* d_in, const int* in_sizes, int n_in,
                              void* d_out, int out_size) {
    const float* x   = (const float*)d_in[0];       // (32, 4096, 3) f32
    const float* psi = (const float*)d_in[1];       // (4096,) f32
    float* out = (float*)d_out;

    static int smem_set = 0;
    int dynsmem = (2 * SDXP + 9 * SESTR) * (int)sizeof(float);   // ~78.3 KB
    if (!smem_set) {
        cudaFuncSetAttribute(k_apply, cudaFuncAttributeMaxDynamicSharedMemorySize, dynsmem);
        smem_set = 1;
    }

    k_setup<<<1, 256>>>();
    k_buildkern<<<NSC, 256>>>(psi);
    int dxtot = NROW * DXSTR;
    k_dx<<<(dxtot + 255) / 256, 256>>>(x);
    k_ebuild<<<dim3(9, NSC), 128>>>();
    k_apply<<<dim3(NROW / 2, NSC), ATHR, dynsmem>>>();
    k_resize_h<<<(OUTN + 255) / 256, 256>>>(out);
}

// round 4
// speedup vs baseline: 2.7865x; 2.0796x over previous
#include <cuda_runtime.h>
#include <math.h>

// ---------------- static configuration ----------------
#define Bn     32
#define Tn     4096
#define Cn     3
#define NSC    128
#define NPSI   4096
#define PADL   2047
#define LP     8190           // Tn + 2*PADL
#define DXSTR  8192
#define NROW   96             // Cn * Bn
#define OUTH   224
#define OUTW   224
#define OUTN   (Bn*OUTH*OUTW*Cn)

#define EKSTR  5504           // per-(scale,class) E stride (zero padded)
#define KMAX   3268           // >= max kernel length 3265
#define UC     1536           // u-chunk
#define UCW    (UC+136)       // sdx words per row (1672, mod 32 = 8)
#define SEW    (UC+392)       // sE words per class (1928, mod 32 = 8)
#define ATHR   224            // 7 warps (one per class)

// ---------------- device scratch ----------------
__device__ __align__(16) float g_dx[NROW * DXSTR + 4096];   // padded (zero-init)
__device__ __align__(16) float g_ek[(size_t)NSC * 9 * EKSTR]; // 25 MB
__device__ float  g_tmpA[NSC * NROW * OUTW];
__device__ int    g_n[NSC];
__device__ int    g_d0[NSC];
__device__ float  g_nsq[NSC];
__device__ double g_sden[NSC];
__device__ float  g_wt[OUTW * 40];
__device__ int    g_wst[OUTW];
__device__ int    g_wcnt[OUTW];
__device__ int    g_whi[OUTH * 2];
__device__ float  g_whw[OUTH * 2];

// ---------------- setup: scales, resize weights ----------------
__global__ void k_setup() {
    int tid = threadIdx.x;
    if (tid < NSC) {
        double l2 = log10(2.0), lM = log10(204.0);
        double y = (tid == NSC - 1) ? lM : (l2 + (double)tid * ((lM - l2) / (double)(NSC - 1)));
        float  sf = (float)pow(10.0, y);
        double sd = (double)sf;
        int n = (int)ceil(sd * 16.0 + 1.0);
        int d0 = (4094 - n) / 2; if (d0 < 0) d0 = 0;
        g_n[tid]   = n;
        g_d0[tid]  = d0;
        g_nsq[tid] = -sqrtf(sf);
        g_sden[tid] = sd * (16.0 / 4095.0);
    }
    if (tid < OUTW) {
        double inv = 4096.0 / 224.0;
        double ks  = inv;
        double sf  = ((double)tid + 0.5) * inv - 0.5;
        int lo = (int)ceil(sf - ks);  if (lo < 0) lo = 0;
        int hi = (int)floor(sf + ks); if (hi > Tn - 1) hi = Tn - 1;
        double tot = 0.0;
        for (int i = lo; i <= hi; i++) {
            double w = 1.0 - fabs((double)i - sf) / ks; if (w < 0.0) w = 0.0;
            tot += w;
        }
        int cnt = hi - lo + 1;
        g_wst[tid] = lo; g_wcnt[tid] = cnt;
        for (int j = 0; j < cnt; j++) {
            double w = 1.0 - fabs((double)(lo + j) - sf) / ks; if (w < 0.0) w = 0.0;
            g_wt[tid * 40 + j] = (float)(w / tot);
        }
        for (int j = cnt; j < 40; j++) g_wt[tid * 40 + j] = 0.0f;
    }
    if (tid < OUTH) {
        double inv = 128.0 / 224.0;
        double sf  = ((double)tid + 0.5) * inv - 0.5;
        int ia = (int)floor(sf);
        int i0 = ia, i1 = ia + 1;
        double w0 = 1.0 - (sf - (double)ia);
        double w1 = sf - (double)ia;
        bool v0 = (i0 >= 0 && i0 < NSC);
        bool v1 = (i1 >= 0 && i1 < NSC);
        double tot = (v0 ? w0 : 0.0) + (v1 ? w1 : 0.0);
        int   o0 = v0 ? i0 : (v1 ? i1 : 0);
        int   o1 = v1 ? i1 : (v0 ? i0 : 0);
        float f0 = v0 ? (float)(w0 / tot) : 0.0f;
        float f1 = v1 ? (float)(w1 / tot) : 0.0f;
        if (!v0 && v1) { f0 = (float)(w1 / tot); f1 = 0.0f; }
        g_whi[tid * 2 + 0] = o0; g_whi[tid * 2 + 1] = o1;
        g_whw[tid * 2 + 0] = f0; g_whw[tid * 2 + 1] = f1;
    }
}

// ---------------- dx = diff(reflect_pad(x)) ----------------
__device__ __forceinline__ float xp_val(const float* __restrict__ x, int b, int c, int p) {
    int i = p - PADL;
    if (i < 0) i = -i;
    else if (i >= Tn) i = 2 * (Tn - 1) - i;
    return x[((size_t)b * Tn + i) * Cn + c];
}

__global__ void k_dx(const float* __restrict__ x) {
    int idx = blockIdx.x * blockDim.x + threadIdx.x;
    if (idx >= NROW * DXSTR) return;
    int r = idx >> 13;
    int p = idx & (DXSTR - 1);
    int c = r / Bn, b = r % Bn;
    float v = 0.0f;
    if (p <= LP - 2) v = xp_val(x, b, c, p + 1) - xp_val(x, b, c, p);
    g_dx[idx] = v;
}

// ---------------- build resize-folded kernels E per (scale, class) ----------------
// classes 0..6: representative w=7+c (interior, exact period 7 in w <-> 128 in t).
//   stored with offset 384 + sh (sh = (d0+st-128)&3) so apply reads EE[u+384-128*delta].
// classes 7,8: edge w=0 / w=223, stored with offset sh only (for fixup kernel).
__global__ __launch_bounds__(ATHR) void k_ebuild(const float* __restrict__ psi) {
    __shared__ float skern[KMAX];
    __shared__ float swt[40];
    int cls = blockIdx.x;
    int sc  = blockIdx.y;
    int tid = threadIdx.x;
    int n = g_n[sc], d0 = g_d0[sc];
    double den = g_sden[sc];
    float nsq = g_nsq[sc];
    int wrep = (cls < 7) ? (7 + cls) : ((cls == 7) ? 0 : 223);
    int st = g_wst[wrep], cnt = g_wcnt[wrep];

    for (int k = tid; k < n; k += ATHR) {
        int m = n - 1 - k;                                  // flip
        int j = (int)floor((double)m / den);
        if (j < 0) j = 0;
        if (j > NPSI - 1) j = NPSI - 1;
        skern[k] = psi[j];
    }
    if (tid < 40) swt[tid] = g_wt[wrep * 40 + tid];
    __syncthreads();

    int A   = (cls < 7) ? (d0 + st - 128) : (d0 + st);
    int sh  = A & 3;
    int off = (cls < 7) ? (384 + sh) : sh;
    int len = n + cnt - 1;

    float* dst = g_ek + ((size_t)(sc * 9 + cls)) * EKSTR;
    for (int v = tid; v < EKSTR; v += ATHR) {
        int p = v - off;
        float acc = 0.0f;
        if (p >= 0 && p < len) {
            int t0 = p - (n - 1); if (t0 < 0) t0 = 0;
            int t1 = p; if (t1 > cnt - 1) t1 = cnt - 1;
            for (int t = t0; t <= t1; t++) acc += swt[t] * skern[p - t];
            acc *= nsq;
        }
        dst[v] = acc;
    }
}

// ---------------- main apply ----------------
// tmpA[sc,row,7j+c] = sum_u dx[row, (Ac&~3)+128j0+u] * EE_c[u+384-128*(j-j0)]
// block = (scale, rowgroup(8) x jquad(4)); warp = class c; lanes split u (contiguous).
extern __shared__ float sm[];
__global__ __launch_bounds__(ATHR, 2) void k_apply() {
    int sc  = blockIdx.y;
    int rg  = blockIdx.x >> 3;
    int jq  = blockIdx.x & 7;
    int j0  = jq * 4;
    int row0 = rg * 8;
    int tid = threadIdx.x;
    int c   = tid >> 5;
    int lane = tid & 31;
    int tid4 = tid * 4;

    int n  = g_n[sc], d0 = g_d0[sc];
    int A     = d0 + g_wst[7 + c] - 128;
    int minA4 = (d0 + g_wst[7] - 128) & ~3;
    int coff  = (A & ~3) - minA4;                  // [0,~112], mult of 4
    int dxbase = minA4 + 128 * j0;
    int ULEN  = (n + 423 + 127) & ~127;

    float* sdx = sm;                  // 8 rows x UCW
    float* sE  = sm + 8 * UCW;        // 7 classes x SEW

    float acc[8][4];
    #pragma unroll
    for (int r = 0; r < 8; r++) {
        acc[r][0] = 0.f; acc[r][1] = 0.f; acc[r][2] = 0.f; acc[r][3] = 0.f;
    }

    for (int U0 = 0; U0 < ULEN; U0 += UC) {
        __syncthreads();
        #pragma unroll
        for (int r = 0; r < 8; r++) {
            const float* src = g_dx + (size_t)(row0 + r) * DXSTR + dxbase + U0;
            for (int i = tid4; i < UCW; i += ATHR * 4)
                *(float4*)(sdx + r * UCW + i) = *(const float4*)(src + i);
        }
        #pragma unroll
        for (int cc = 0; cc < 7; cc++) {
            const float* esrc = g_ek + ((size_t)(sc * 9 + cc)) * EKSTR + U0;
            for (int i = tid4; i < SEW; i += ATHR * 4)
                *(float4*)(sE + cc * SEW + i) = *(const float4*)(esrc + i);
        }
        __syncthreads();

        int rem = ULEN - U0;
        int kmax = ((rem < UC) ? rem : UC) >> 7;
        const float* sEc = sE + c * SEW;
        const float* sdc = sdx + coff;

        for (int k = 0; k < kmax; k++) {
            int ub = (k << 7) + (lane << 2);
            float4 e0 = *(const float4*)(sEc + ub + 384);
            float4 e1 = *(const float4*)(sEc + ub + 256);
            float4 e2 = *(const float4*)(sEc + ub + 128);
            float4 e3 = *(const float4*)(sEc + ub);
            #pragma unroll
            for (int r = 0; r < 8; r++) {
                float4 d = *(const float4*)(sdc + r * UCW + ub);
                acc[r][0] = fmaf(d.x, e0.x, fmaf(d.y, e0.y, fmaf(d.z, e0.z, fmaf(d.w, e0.w, acc[r][0]))));
                acc[r][1] = fmaf(d.x, e1.x, fmaf(d.y, e1.y, fmaf(d.z, e1.z, fmaf(d.w, e1.w, acc[r][1]))));
                acc[r][2] = fmaf(d.x, e2.x, fmaf(d.y, e2.y, fmaf(d.z, e2.z, fmaf(d.w, e2.w, acc[r][2]))));
                acc[r][3] = fmaf(d.x, e3.x, fmaf(d.y, e3.y, fmaf(d.z, e3.z, fmaf(d.w, e3.w, acc[r][3]))));
            }
        }
    }

    // cross-lane reduction via bank-staggered smem transpose (stride 33)
    __syncthreads();
    float* sred = sm;                 // 7 * 1056 floats, fits in sdx region
    #pragma unroll
    for (int r = 0; r < 8; r++) {
        #pragma unroll
        for (int dlt = 0; dlt < 4; dlt++)
            sred[c * 1056 + (r * 4 + dlt) * 33 + lane] = acc[r][dlt];
    }
    __syncthreads();
    {
        int c2 = tid >> 5;            // class
        int u2 = tid & 31;            // (r,delta)
        const float* p = sred + c2 * 1056 + u2 * 33;
        float s = 0.f;
        #pragma unroll
        for (int i = 0; i < 32; i++) s += p[i];
        int r2 = u2 >> 2, d2 = u2 & 3;
        int w = 7 * (j0 + d2) + c2;
        g_tmpA[(sc * NROW + row0 + r2) * OUTW + w] = s;
    }
}

// ---------------- exact fixup for clipped edge columns w=0, w=223 ----------------
__global__ void k_fixup() {
    __shared__ float se[3328];
    int e  = blockIdx.x;              // 0 -> w=0 (class 7), 1 -> w=223 (class 8)
    int sc = blockIdx.y;
    int tid = threadIdx.x;
    int cls = 7 + e;
    int wE = e ? 223 : 0;
    int n = g_n[sc], d0 = g_d0[sc];
    int st = g_wst[wE], cnt = g_wcnt[wE];
    int base = (d0 + st) & ~3;
    int sh = (d0 + st) & 3;
    int qmax = sh + n + cnt - 1;

    const float* esrc = g_ek + ((size_t)(sc * 9 + cls)) * EKSTR;
    for (int i = tid * 4; i < 3328; i += 1024)
        *(float4*)(se + i) = *(const float4*)(esrc + i);
    __syncthreads();

    int wi = tid >> 5, lane = tid & 31;
    for (int row = wi; row < NROW; row += 8) {
        const float* dxr = g_dx + (size_t)row * DXSTR + base;
        float p = 0.f;
        for (int q = lane * 4; q < qmax; q += 128) {
            float4 d = *(const float4*)(dxr + q);
            float4 ev = *(const float4*)(se + q);
            p = fmaf(d.x, ev.x, fmaf(d.y, ev.y, fmaf(d.z, ev.z, fmaf(d.w, ev.w, p))));
        }
        #pragma unroll
        for (int o = 16; o > 0; o >>= 1) p += __shfl_xor_sync(0xffffffffu, p, o);
        if (lane == 0) g_tmpA[(sc * NROW + row) * OUTW + wE] = p;
    }
}

// ---------------- resize stage B: scale axis 128 -> 224 ----------------
__global__ void k_resize_h(float* __restrict__ out) {
    int idx = blockIdx.x * blockDim.x + threadIdx.x;
    if (idx >= OUTN) return;
    int c = idx % Cn;
    int w = (idx / Cn) % OUTW;
    int h = (idx / (Cn * OUTW)) % OUTH;
    int b = idx / (Cn * OUTW * OUTH);
    int i0 = g_whi[h * 2 + 0], i1 = g_whi[h * 2 + 1];
    float f0 = g_whw[h * 2 + 0], f1 = g_whw[h * 2 + 1];
    int rb = (c * Bn + b) * OUTW + w;
    out[idx] = f0 * g_tmpA[i0 * NROW * OUTW + rb] + f1 * g_tmpA[i1 * NROW * OUTW + rb];
}

// ---------------- launch ----------------
extern "C" void kernel_launch(void* const* d_in, const int* in_sizes, int n_in,
                              void* d_out, int out_size) {
    const float* x   = (const float*)d_in[0];       // (32, 4096, 3) f32
    const float* psi = (const float*)d_in[1];       // (4096,) f32
    float* out = (float*)d_out;

    static int smem_set = 0;
    int dynsmem = (8 * UCW + 7 * SEW) * (int)sizeof(float);   // 107488 B
    if (!smem_set) {
        cudaFuncSetAttribute(k_apply, cudaFuncAttributeMaxDynamicSharedMemorySize, dynsmem);
        smem_set = 1;
    }

    k_setup<<<1, 256>>>();
    k_dx<<<(NROW * DXSTR + 255) / 256, 256>>>(x);
    k_ebuild<<<dim3(9, NSC), ATHR>>>(psi);
    k_apply<<<dim3(96, NSC), ATHR, dynsmem>>>();     // launch #3 -> ncu captures this
    k_fixup<<<dim3(2, NSC), 256>>>();
    k_resize_h<<<(OUTN + 255) / 256, 256>>>(out);
}

// round 5
// speedup vs baseline: 2.8186x; 1.0115x over previous
#include <cuda_runtime.h>
#include <math.h>

// ---------------- static configuration ----------------
#define Bn     32
#define Tn     4096
#define Cn     3
#define NSC    128
#define NPSI   4096
#define PADL   2047
#define LP     8190           // Tn + 2*PADL
#define DXSTR  8192
#define NROW   96             // Cn * Bn
#define OUTH   224
#define OUTW   224
#define OUTN   (Bn*OUTH*OUTW*Cn)

#define EKSTR  5248           // per-(scale,class) E stride (zero padded)
#define KMAX   3268           // >= max kernel length 3265
#define UC     1024           // u-chunk
#define UCW    (UC+136)       // sdx words per row (1160, mod 32 = 8)
#define SEW    (UC+936)       // sE words per class (1960, mod 32 = 8)
#define ATHR   224            // 7 warps (one per class)

// ---------------- device scratch ----------------
__device__ __align__(16) float g_dx[NROW * DXSTR + 4096];     // padded, zero-init
__device__ __align__(16) float g_ek[(size_t)NSC * 9 * EKSTR + 4096]; // ~24 MB, padded
__device__ float  g_tmpA[NSC * NROW * OUTW];
__device__ int    g_n[NSC];
__device__ int    g_d0[NSC];
__device__ float  g_nsq[NSC];
__device__ double g_sden[NSC];
__device__ float  g_wt[OUTW * 40];
__device__ int    g_wst[OUTW];
__device__ int    g_wcnt[OUTW];
__device__ int    g_whi[OUTH * 2];
__device__ float  g_whw[OUTH * 2];

// ---------------- setup: scales, resize weights ----------------
__global__ void k_setup() {
    int tid = threadIdx.x;
    if (tid < NSC) {
        double l2 = log10(2.0), lM = log10(204.0);
        double y = (tid == NSC - 1) ? lM : (l2 + (double)tid * ((lM - l2) / (double)(NSC - 1)));
        float  sf = (float)pow(10.0, y);
        double sd = (double)sf;
        int n = (int)ceil(sd * 16.0 + 1.0);
        int d0 = (4094 - n) / 2; if (d0 < 0) d0 = 0;
        g_n[tid]   = n;
        g_d0[tid]  = d0;
        g_nsq[tid] = -sqrtf(sf);
        g_sden[tid] = sd * (16.0 / 4095.0);
    }
    if (tid < OUTW) {
        double inv = 4096.0 / 224.0;
        double ks  = inv;
        double sf  = ((double)tid + 0.5) * inv - 0.5;
        int lo = (int)ceil(sf - ks);  if (lo < 0) lo = 0;
        int hi = (int)floor(sf + ks); if (hi > Tn - 1) hi = Tn - 1;
        double tot = 0.0;
        for (int i = lo; i <= hi; i++) {
            double w = 1.0 - fabs((double)i - sf) / ks; if (w < 0.0) w = 0.0;
            tot += w;
        }
        int cnt = hi - lo + 1;
        g_wst[tid] = lo; g_wcnt[tid] = cnt;
        for (int j = 0; j < cnt; j++) {
            double w = 1.0 - fabs((double)(lo + j) - sf) / ks; if (w < 0.0) w = 0.0;
            g_wt[tid * 40 + j] = (float)(w / tot);
        }
        for (int j = cnt; j < 40; j++) g_wt[tid * 40 + j] = 0.0f;
    }
    if (tid < OUTH) {
        double inv = 128.0 / 224.0;
        double sf  = ((double)tid + 0.5) * inv - 0.5;
        int ia = (int)floor(sf);
        int i0 = ia, i1 = ia + 1;
        double w0 = 1.0 - (sf - (double)ia);
        double w1 = sf - (double)ia;
        bool v0 = (i0 >= 0 && i0 < NSC);
        bool v1 = (i1 >= 0 && i1 < NSC);
        double tot = (v0 ? w0 : 0.0) + (v1 ? w1 : 0.0);
        int   o0 = v0 ? i0 : (v1 ? i1 : 0);
        int   o1 = v1 ? i1 : (v0 ? i0 : 0);
        float f0 = v0 ? (float)(w0 / tot) : 0.0f;
        float f1 = v1 ? (float)(w1 / tot) : 0.0f;
        if (!v0 && v1) { f0 = (float)(w1 / tot); f1 = 0.0f; }
        g_whi[tid * 2 + 0] = o0; g_whi[tid * 2 + 1] = o1;
        g_whw[tid * 2 + 0] = f0; g_whw[tid * 2 + 1] = f1;
    }
}

// ---------------- dx = diff(reflect_pad(x)) ----------------
__device__ __forceinline__ float xp_val(const float* __restrict__ x, int b, int c, int p) {
    int i = p - PADL;
    if (i < 0) i = -i;
    else if (i >= Tn) i = 2 * (Tn - 1) - i;
    return x[((size_t)b * Tn + i) * Cn + c];
}

__global__ void k_dx(const float* __restrict__ x) {
    int idx = blockIdx.x * blockDim.x + threadIdx.x;
    if (idx >= NROW * DXSTR) return;
    int r = idx >> 13;
    int p = idx & (DXSTR - 1);
    int c = r / Bn, b = r % Bn;
    float v = 0.0f;
    if (p <= LP - 2) v = xp_val(x, b, c, p + 1) - xp_val(x, b, c, p);
    g_dx[idx] = v;
}

// ---------------- build resize-folded kernels E per (scale, class) ----------------
// classes 0..6: representative w=7+c, stored with offset 896 + sh
//   (sh = (d0+st-128)&3) so apply reads EE[u + 896 - 128*dj], dj = 0..7.
// classes 7,8: edge w=0 / w=223, stored with offset sh only (fixup kernel).
__global__ __launch_bounds__(ATHR) void k_ebuild(const float* __restrict__ psi) {
    __shared__ float skern[KMAX];
    __shared__ float swt[40];
    int cls = blockIdx.x;
    int sc  = blockIdx.y;
    int tid = threadIdx.x;
    int n = g_n[sc], d0 = g_d0[sc];
    double den = g_sden[sc];
    float nsq = g_nsq[sc];
    int wrep = (cls < 7) ? (7 + cls) : ((cls == 7) ? 0 : 223);
    int st = g_wst[wrep], cnt = g_wcnt[wrep];

    for (int k = tid; k < n; k += ATHR) {
        int m = n - 1 - k;                                  // flip
        int j = (int)floor((double)m / den);
        if (j < 0) j = 0;
        if (j > NPSI - 1) j = NPSI - 1;
        skern[k] = psi[j];
    }
    if (tid < 40) swt[tid] = g_wt[wrep * 40 + tid];
    __syncthreads();

    int A   = (cls < 7) ? (d0 + st - 128) : (d0 + st);
    int sh  = A & 3;
    int off = (cls < 7) ? (896 + sh) : sh;
    int len = n + cnt - 1;

    float* dst = g_ek + ((size_t)(sc * 9 + cls)) * EKSTR;
    for (int v = tid; v < EKSTR; v += ATHR) {
        int p = v - off;
        float acc = 0.0f;
        if (p >= 0 && p < len) {
            int t0 = p - (n - 1); if (t0 < 0) t0 = 0;
            int t1 = p; if (t1 > cnt - 1) t1 = cnt - 1;
            for (int t = t0; t <= t1; t++) acc += swt[t] * skern[p - t];
            acc *= nsq;
        }
        dst[v] = acc;
    }
}

// ---------------- main apply ----------------
// tmpA[sc,row,7(j0+dj)+c] = sum_u dx[row, minA4+128j0+coff_c+u] * EE_c[u+896-128dj]
// block = (scale, rowgroup(8) x joct(8)); warp = class c; lanes split u contiguously.
extern __shared__ float sm[];
__global__ __launch_bounds__(ATHR, 2) void k_apply() {
    int sc  = blockIdx.y;
    int rg  = blockIdx.x >> 2;           // 12 rowgroups of 8
    int jq  = blockIdx.x & 3;            // 4 octets of j
    int j0  = jq * 8;
    int row0 = rg * 8;
    int tid = threadIdx.x;
    int c   = tid >> 5;
    int lane = tid & 31;
    int tid4 = tid * 4;

    int n  = g_n[sc], d0 = g_d0[sc];
    int A     = d0 + g_wst[7 + c] - 128;
    int minA4 = (d0 + g_wst[7] - 128) & ~3;
    int coff  = (A & ~3) - minA4;        // [0,~116], mult of 4
    int dxbase = minA4 + 128 * j0;
    int ULEN  = (n + 937 + 127) & ~127;  // covers dj=7 shift + support + slack

    float* sdx = sm;                     // 8 rows x UCW
    float* sE  = sm + 8 * UCW;           // 7 classes x SEW

    float acc[8][8];
    #pragma unroll
    for (int r = 0; r < 8; r++)
        #pragma unroll
        for (int dj = 0; dj < 8; dj++) acc[r][dj] = 0.f;

    for (int U0 = 0; U0 < ULEN; U0 += UC) {
        __syncthreads();
        #pragma unroll
        for (int r = 0; r < 8; r++) {
            const float* src = g_dx + (size_t)(row0 + r) * DXSTR + dxbase + U0;
            for (int i = tid4; i < UCW; i += ATHR * 4)
                *(float4*)(sdx + r * UCW + i) = *(const float4*)(src + i);
        }
        #pragma unroll
        for (int cc = 0; cc < 7; cc++) {
            const float* esrc = g_ek + ((size_t)(sc * 9 + cc)) * EKSTR + U0;
            for (int i = tid4; i < SEW; i += ATHR * 4)
                *(float4*)(sE + cc * SEW + i) = *(const float4*)(esrc + i);
        }
        __syncthreads();

        int rem = ULEN - U0;
        int kmax = ((rem < UC) ? rem : UC) >> 7;
        const float* sEc = sE + c * SEW;
        const float* sdc = sdx + coff;

        for (int k = 0; k < kmax; k++) {
            int ub = (k << 7) + (lane << 2);
            float4 e0 = *(const float4*)(sEc + ub + 896);
            float4 e1 = *(const float4*)(sEc + ub + 768);
            float4 e2 = *(const float4*)(sEc + ub + 640);
            float4 e3 = *(const float4*)(sEc + ub + 512);
            float4 e4 = *(const float4*)(sEc + ub + 384);
            float4 e5 = *(const float4*)(sEc + ub + 256);
            float4 e6 = *(const float4*)(sEc + ub + 128);
            float4 e7 = *(const float4*)(sEc + ub);
            #pragma unroll
            for (int r = 0; r < 8; r++) {
                float4 d = *(const float4*)(sdc + r * UCW + ub);
                acc[r][0] = fmaf(d.x, e0.x, fmaf(d.y, e0.y, fmaf(d.z, e0.z, fmaf(d.w, e0.w, acc[r][0]))));
                acc[r][1] = fmaf(d.x, e1.x, fmaf(d.y, e1.y, fmaf(d.z, e1.z, fmaf(d.w, e1.w, acc[r][1]))));
                acc[r][2] = fmaf(d.x, e2.x, fmaf(d.y, e2.y, fmaf(d.z, e2.z, fmaf(d.w, e2.w, acc[r][2]))));
                acc[r][3] = fmaf(d.x, e3.x, fmaf(d.y, e3.y, fmaf(d.z, e3.z, fmaf(d.w, e3.w, acc[r][3]))));
                acc[r][4] = fmaf(d.x, e4.x, fmaf(d.y, e4.y, fmaf(d.z, e4.z, fmaf(d.w, e4.w, acc[r][4]))));
                acc[r][5] = fmaf(d.x, e5.x, fmaf(d.y, e5.y, fmaf(d.z, e5.z, fmaf(d.w, e5.w, acc[r][5]))));
                acc[r][6] = fmaf(d.x, e6.x, fmaf(d.y, e6.y, fmaf(d.z, e6.z, fmaf(d.w, e6.w, acc[r][6]))));
                acc[r][7] = fmaf(d.x, e7.x, fmaf(d.y, e7.y, fmaf(d.z, e7.z, fmaf(d.w, e7.w, acc[r][7]))));
            }
        }
    }

    // cross-lane reduction via bank-staggered smem transpose (stride 33)
    __syncthreads();
    float* sred = sm;                    // 7 * 2112 floats (fits: 14784 < 23000)
    #pragma unroll
    for (int r = 0; r < 8; r++)
        #pragma unroll
        for (int dj = 0; dj < 8; dj++)
            sred[c * 2112 + (r * 8 + dj) * 33 + lane] = acc[r][dj];
    __syncthreads();
    for (int o = tid; o < 448; o += ATHR) {
        int c2 = o >> 6;
        int u2 = o & 63;
        const float* p = sred + c2 * 2112 + u2 * 33;
        float s = 0.f;
        #pragma unroll
        for (int i = 0; i < 32; i++) s += p[i];
        int r2 = u2 >> 3, d2 = u2 & 7;
        int w = 7 * (j0 + d2) + c2;
        g_tmpA[(sc * NROW + row0 + r2) * OUTW + w] = s;
    }
}

// ---------------- exact fixup for clipped edge columns w=0, w=223 ----------------
__global__ void k_fixup() {
    __shared__ float se[3328];
    int e  = blockIdx.x;              // 0 -> w=0 (class 7), 1 -> w=223 (class 8)
    int sc = blockIdx.y;
    int tid = threadIdx.x;
    int cls = 7 + e;
    int wE = e ? 223 : 0;
    int n = g_n[sc], d0 = g_d0[sc];
    int st = g_wst[wE], cnt = g_wcnt[wE];
    int base = (d0 + st) & ~3;
    int sh = (d0 + st) & 3;
    int qmax = sh + n + cnt - 1;

    const float* esrc = g_ek + ((size_t)(sc * 9 + cls)) * EKSTR;
    for (int i = tid * 4; i < 3328; i += 1024)
        *(float4*)(se + i) = *(const float4*)(esrc + i);
    __syncthreads();

    int wi = tid >> 5, lane = tid & 31;
    for (int row = wi; row < NROW; row += 8) {
        const float* dxr = g_dx + (size_t)row * DXSTR + base;
        float p = 0.f;
        for (int q = lane * 4; q < qmax; q += 128) {
            float4 d = *(const float4*)(dxr + q);
            float4 ev = *(const float4*)(se + q);
            p = fmaf(d.x, ev.x, fmaf(d.y, ev.y, fmaf(d.z, ev.z, fmaf(d.w, ev.w, p))));
        }
        #pragma unroll
        for (int o = 16; o > 0; o >>= 1) p += __shfl_xor_sync(0xffffffffu, p, o);
        if (lane == 0) g_tmpA[(sc * NROW + row) * OUTW + wE] = p;
    }
}

// ---------------- resize stage B: scale axis 128 -> 224 ----------------
__global__ void k_resize_h(float* __restrict__ out) {
    int idx = blockIdx.x * blockDim.x + threadIdx.x;
    if (idx >= OUTN) return;
    int c = idx % Cn;
    int w = (idx / Cn) % OUTW;
    int h = (idx / (Cn * OUTW)) % OUTH;
    int b = idx / (Cn * OUTW * OUTH);
    int i0 = g_whi[h * 2 + 0], i1 = g_whi[h * 2 + 1];
    float f0 = g_whw[h * 2 + 0], f1 = g_whw[h * 2 + 1];
    int rb = (c * Bn + b) * OUTW + w;
    out[idx] = f0 * g_tmpA[i0 * NROW * OUTW + rb] + f1 * g_tmpA[i1 * NROW * OUTW + rb];
}

// ---------------- launch ----------------
extern "C" void kernel_launch(void* const* d_in, const int* in_sizes, int n_in,
                              void* d_out, int out_size) {
    const float* x   = (const float*)d_in[0];       // (32, 4096, 3) f32
    const float* psi = (const float*)d_in[1];       // (4096,) f32
    float* out = (float*)d_out;

    static int smem_set = 0;
    int dynsmem = (8 * UCW + 7 * SEW) * (int)sizeof(float);   // 92000 B
    if (!smem_set) {
        cudaFuncSetAttribute(k_apply, cudaFuncAttributeMaxDynamicSharedMemorySize, dynsmem);
        smem_set = 1;
    }

    k_setup<<<1, 256>>>();
    k_dx<<<(NROW * DXSTR + 255) / 256, 256>>>(x);
    k_ebuild<<<dim3(9, NSC), ATHR>>>(psi);
    k_apply<<<dim3(48, NSC), ATHR, dynsmem>>>();     // launch #3 -> ncu captures this
    k_fixup<<<dim3(2, NSC), 256>>>();
    k_resize_h<<<(OUTN + 255) / 256, 256>>>(out);
}

// round 6
// speedup vs baseline: 4.0587x; 1.4400x over previous
#include <cuda_runtime.h>
#include <math.h>

// ---------------- static configuration ----------------
#define Bn     32
#define Tn     4096
#define Cn     3
#define NSC    128
#define NPSI   4096
#define PADL   2047
#define LP     8190           // Tn + 2*PADL
#define DXSTR  8192
#define NROW   96             // Cn * Bn
#define OUTH   224
#define OUTW   224
#define OUTN   (Bn*OUTH*OUTW*Cn)

#define U0     384            // global u-grid origin (min A = 405 > 384)
#define KE     3456           // Ê u-extent (max end 3817-384=3433 < 3456)
#define MTOT   896            // 128 scales x 7 interior classes
#define KMAX   3268           // >= max wavelet kernel length 3265
#define EKE    3328           // edge-kernel stride (fixup)

#define BM     128
#define BN     64
#define BK     16
#define SAST   132            // sA row stride (pad)
#define SBST   68             // sB row stride (pad)

// ---------------- device scratch ----------------
__device__ __align__(16) float g_dx[NROW * DXSTR + 4096];      // 3 MB (zero-init)
__device__ __align__(16) float g_ehT[(size_t)KE * MTOT + 64];  // 12.4 MB  [u][m]
__device__ __align__(16) float g_eke[NSC * 2 * EKE];           // 3.4 MB edge kernels
__device__ float  g_tmpA[NSC * NROW * OUTW];                   // 11 MB
__device__ int    g_n[NSC];
__device__ int    g_d0[NSC];
__device__ float  g_nsq[NSC];
__device__ double g_sden[NSC];
__device__ float  g_wt[OUTW * 40];
__device__ int    g_wst[OUTW];
__device__ int    g_wcnt[OUTW];
__device__ int    g_whi[OUTH * 2];
__device__ float  g_whw[OUTH * 2];
__device__ int    g_tk[7 * 2];                                 // per-M-tile K window

// ---------------- setup: scales, resize weights, tile K-windows ----------------
__global__ void k_setup() {
    int tid = threadIdx.x;
    if (tid < NSC) {
        double l2 = log10(2.0), lM = log10(204.0);
        double y = (tid == NSC - 1) ? lM : (l2 + (double)tid * ((lM - l2) / (double)(NSC - 1)));
        float  sf = (float)pow(10.0, y);
        double sd = (double)sf;
        int n = (int)ceil(sd * 16.0 + 1.0);
        int d0 = (4094 - n) / 2; if (d0 < 0) d0 = 0;
        g_n[tid]   = n;
        g_d0[tid]  = d0;
        g_nsq[tid] = -sqrtf(sf);
        g_sden[tid] = sd * (16.0 / 4095.0);
    }
    if (tid < OUTW) {
        double inv = 4096.0 / 224.0;
        double ks  = inv;
        double sf  = ((double)tid + 0.5) * inv - 0.5;
        int lo = (int)ceil(sf - ks);  if (lo < 0) lo = 0;
        int hi = (int)floor(sf + ks); if (hi > Tn - 1) hi = Tn - 1;
        double tot = 0.0;
        for (int i = lo; i <= hi; i++) {
            double w = 1.0 - fabs((double)i - sf) / ks; if (w < 0.0) w = 0.0;
            tot += w;
        }
        int cnt = hi - lo + 1;
        g_wst[tid] = lo; g_wcnt[tid] = cnt;
        for (int j = 0; j < cnt; j++) {
            double w = 1.0 - fabs((double)(lo + j) - sf) / ks; if (w < 0.0) w = 0.0;
            g_wt[tid * 40 + j] = (float)(w / tot);
        }
        for (int j = cnt; j < 40; j++) g_wt[tid * 40 + j] = 0.0f;
    }
    if (tid < OUTH) {
        double inv = 128.0 / 224.0;
        double sf  = ((double)tid + 0.5) * inv - 0.5;
        int ia = (int)floor(sf);
        int i0 = ia, i1 = ia + 1;
        double w0 = 1.0 - (sf - (double)ia);
        double w1 = sf - (double)ia;
        bool v0 = (i0 >= 0 && i0 < NSC);
        bool v1 = (i1 >= 0 && i1 < NSC);
        double tot = (v0 ? w0 : 0.0) + (v1 ? w1 : 0.0);
        int   o0 = v0 ? i0 : (v1 ? i1 : 0);
        int   o1 = v1 ? i1 : (v0 ? i0 : 0);
        float f0 = v0 ? (float)(w0 / tot) : 0.0f;
        float f1 = v1 ? (float)(w1 / tot) : 0.0f;
        if (!v0 && v1) { f0 = (float)(w1 / tot); f1 = 0.0f; }
        g_whi[tid * 2 + 0] = o0; g_whi[tid * 2 + 1] = o1;
        g_whw[tid * 2 + 0] = f0; g_whw[tid * 2 + 1] = f1;
    }
    __syncthreads();
    if (tid < 7) {
        int smin = (BM * tid) / 7;
        int smax = (BM * tid + BM - 1) / 7; if (smax > NSC - 1) smax = NSC - 1;
        int lo = 1 << 30, hi = 0;
        for (int s = smin; s <= smax; s++) {
            for (int c = 0; c < 7; c++) {
                int A = g_d0[s] + g_wst[7 + c] - 128;
                int e = A + g_n[s] + g_wcnt[7 + c] - 1;
                int a0 = A - U0, e0 = e + 1 - U0;
                if (a0 < lo) lo = a0;
                if (e0 > hi) hi = e0;
            }
        }
        g_tk[tid * 2 + 0] = lo & ~15;
        g_tk[tid * 2 + 1] = (hi + 15) & ~15;
    }
}

// ---------------- dx = diff(reflect_pad(x)) ----------------
__device__ __forceinline__ float xp_val(const float* __restrict__ x, int b, int c, int p) {
    int i = p - PADL;
    if (i < 0) i = -i;
    else if (i >= Tn) i = 2 * (Tn - 1) - i;
    return x[((size_t)b * Tn + i) * Cn + c];
}

__global__ void k_dx(const float* __restrict__ x) {
    int idx = blockIdx.x * blockDim.x + threadIdx.x;
    if (idx >= NROW * DXSTR) return;
    int r = idx >> 13;
    int p = idx & (DXSTR - 1);
    int c = r / Bn, b = r % Bn;
    float v = 0.0f;
    if (p <= LP - 2) v = xp_val(x, b, c, p + 1) - xp_val(x, b, c, p);
    g_dx[idx] = v;
}

// ---------------- build resize-folded kernels ----------------
// interior cls 0..6: Ê[m=(s*7+cls)][ug] = W_c[ug - A], A = d0 + st(7+c) - 128
//   written transposed into g_ehT[kg][m], kg = ug - U0, full column incl zeros.
// cls 7/8 (edge w=0 / w=223): g_eke as before (offset sh), for k_fixup.
__global__ __launch_bounds__(256) void k_ebuildT(const float* __restrict__ psi) {
    __shared__ float skern[KMAX];
    __shared__ float swt[40];
    int cls = blockIdx.x;
    int sc  = blockIdx.y;
    int tid = threadIdx.x;
    int n = g_n[sc], d0 = g_d0[sc];
    double den = g_sden[sc];
    float nsq = g_nsq[sc];
    int wrep = (cls < 7) ? (7 + cls) : ((cls == 7) ? 0 : 223);
    int st = g_wst[wrep], cnt = g_wcnt[wrep];

    for (int k = tid; k < n; k += 256) {
        int m = n - 1 - k;                                  // flip
        int j = (int)floor((double)m / den);
        if (j < 0) j = 0;
        if (j > NPSI - 1) j = NPSI - 1;
        skern[k] = psi[j];
    }
    if (tid < 40) swt[tid] = g_wt[wrep * 40 + tid];
    __syncthreads();

    int len = n + cnt - 1;
    if (cls < 7) {
        int A = d0 + st - 128;
        int m = sc * 7 + cls;
        int p0 = A - U0;                 // first nonzero kg
        for (int v = tid; v < KE; v += 256) {
            int p = v - p0;
            float acc = 0.0f;
            if (p >= 0 && p < len) {
                int t0 = p - (n - 1); if (t0 < 0) t0 = 0;
                int t1 = p; if (t1 > cnt - 1) t1 = cnt - 1;
                for (int t = t0; t <= t1; t++) acc += swt[t] * skern[p - t];
                acc *= nsq;
            }
            g_ehT[(size_t)v * MTOT + m] = acc;
        }
    } else {
        int sh = (d0 + st) & 3;
        float* dst = g_eke + (size_t)(sc * 2 + (cls - 7)) * EKE;
        for (int v = tid; v < EKE; v += 256) {
            int p = v - sh;
            float acc = 0.0f;
            if (p >= 0 && p < len) {
                int t0 = p - (n - 1); if (t0 < 0) t0 = 0;
                int t1 = p; if (t1 > cnt - 1) t1 = cnt - 1;
                for (int t = t0; t <= t1; t++) acc += swt[t] * skern[p - t];
                acc *= nsq;
            }
            dst[v] = acc;
        }
    }
}

// ---------------- main GEMM ----------------
// C[m=(s,c)][n=(row,j)] = sum_k Ê[m][k] * dx[row, U0+k+128j],  k in [klo_mt, khi_mt)
__global__ __launch_bounds__(128, 4) void k_gemm() {
    __shared__ float sA[2][BK][SAST];
    __shared__ float sB[2][BK][SBST];

    int nt = blockIdx.x;
    int mt = 6 - blockIdx.y;            // heavy tiles scheduled first
    int klo = g_tk[mt * 2], khi = g_tk[mt * 2 + 1];
    int nk = (khi - klo) >> 4;
    int m0 = mt * BM, n0 = nt * BN;
    int tid = threadIdx.x;
    int warp = tid >> 5, lane = tid & 31;
    int wm = warp >> 1, wn = warp & 1;
    int lm = lane >> 2, ln = lane & 3;
    int m8 = wm * 64 + lm * 8;
    int n8 = wn * 32 + ln * 8;

    // global-load thread mapping
    int mq = tid & 31, kA = tid >> 5;                        // A: k = kA + 4i
    int nb = tid & 63, kh = tid >> 6;                        // B: k = kh*8 + {0..7}
    int ng = n0 + nb; int brow = ng >> 5, bj = ng & 31;

    const float* pA = g_ehT + (size_t)(klo + kA) * MTOT + m0 + mq * 4;
    const float* pB = g_dx + (size_t)brow * DXSTR + U0 + klo + (bj << 7) + kh * 8;

    float4 Ar0, Ar1, Ar2, Ar3, Br0, Br1;
    Ar0 = *(const float4*)(pA);
    Ar1 = *(const float4*)(pA + (size_t)4 * MTOT);
    Ar2 = *(const float4*)(pA + (size_t)8 * MTOT);
    Ar3 = *(const float4*)(pA + (size_t)12 * MTOT);
    Br0 = *(const float4*)(pB);
    Br1 = *(const float4*)(pB + 4);
    {
        *(float4*)&sA[0][kA][mq * 4]      = Ar0;
        *(float4*)&sA[0][kA + 4][mq * 4]  = Ar1;
        *(float4*)&sA[0][kA + 8][mq * 4]  = Ar2;
        *(float4*)&sA[0][kA + 12][mq * 4] = Ar3;
        int k0 = kh * 8;
        sB[0][k0 + 0][nb] = Br0.x; sB[0][k0 + 1][nb] = Br0.y;
        sB[0][k0 + 2][nb] = Br0.z; sB[0][k0 + 3][nb] = Br0.w;
        sB[0][k0 + 4][nb] = Br1.x; sB[0][k0 + 5][nb] = Br1.y;
        sB[0][k0 + 6][nb] = Br1.z; sB[0][k0 + 7][nb] = Br1.w;
    }
    __syncthreads();

    float acc[8][8];
    #pragma unroll
    for (int i = 0; i < 8; i++)
        #pragma unroll
        for (int j = 0; j < 8; j++) acc[i][j] = 0.f;

    for (int kb = 0; kb < nk; kb++) {
        int cur = kb & 1;
        if (kb + 1 < nk) {
            const float* qA = pA + (size_t)(kb + 1) * BK * MTOT;
            const float* qB = pB + (kb + 1) * BK;
            Ar0 = *(const float4*)(qA);
            Ar1 = *(const float4*)(qA + (size_t)4 * MTOT);
            Ar2 = *(const float4*)(qA + (size_t)8 * MTOT);
            Ar3 = *(const float4*)(qA + (size_t)12 * MTOT);
            Br0 = *(const float4*)(qB);
            Br1 = *(const float4*)(qB + 4);
        }
        #pragma unroll
        for (int k = 0; k < BK; k++) {
            float a[8], b[8];
            *(float4*)(a)     = *(const float4*)&sA[cur][k][m8];
            *(float4*)(a + 4) = *(const float4*)&sA[cur][k][m8 + 4];
            *(float4*)(b)     = *(const float4*)&sB[cur][k][n8];
            *(float4*)(b + 4) = *(const float4*)&sB[cur][k][n8 + 4];
            #pragma unroll
            for (int i = 0; i < 8; i++)
                #pragma unroll
                for (int j = 0; j < 8; j++)
                    acc[i][j] = fmaf(a[i], b[j], acc[i][j]);
        }
        if (kb + 1 < nk) {
            int nx = cur ^ 1;
            *(float4*)&sA[nx][kA][mq * 4]      = Ar0;
            *(float4*)&sA[nx][kA + 4][mq * 4]  = Ar1;
            *(float4*)&sA[nx][kA + 8][mq * 4]  = Ar2;
            *(float4*)&sA[nx][kA + 12][mq * 4] = Ar3;
            int k0 = kh * 8;
            sB[nx][k0 + 0][nb] = Br0.x; sB[nx][k0 + 1][nb] = Br0.y;
            sB[nx][k0 + 2][nb] = Br0.z; sB[nx][k0 + 3][nb] = Br0.w;
            sB[nx][k0 + 4][nb] = Br1.x; sB[nx][k0 + 5][nb] = Br1.y;
            sB[nx][k0 + 6][nb] = Br1.z; sB[nx][k0 + 7][nb] = Br1.w;
        }
        __syncthreads();
    }

    // epilogue: scatter into g_tmpA[(s*96+row)*224 + 7*j + c]
    #pragma unroll
    for (int i = 0; i < 8; i++) {
        int m = m0 + m8 + i;
        int s = m / 7;
        int c = m - s * 7;
        #pragma unroll
        for (int j = 0; j < 8; j++) {
            int n = n0 + n8 + j;
            int row = n >> 5, jj = n & 31;
            g_tmpA[(s * NROW + row) * OUTW + 7 * jj + c] = acc[i][j];
        }
    }
}

// ---------------- exact fixup for clipped edge columns w=0, w=223 ----------------
__global__ void k_fixup() {
    __shared__ float se[EKE];
    int e  = blockIdx.x;              // 0 -> w=0, 1 -> w=223
    int sc = blockIdx.y;
    int tid = threadIdx.x;
    int wE = e ? 223 : 0;
    int n = g_n[sc], d0 = g_d0[sc];
    int st = g_wst[wE], cnt = g_wcnt[wE];
    int base = (d0 + st) & ~3;
    int sh = (d0 + st) & 3;
    int qmax = sh + n + cnt - 1;

    const float* esrc = g_eke + (size_t)(sc * 2 + e) * EKE;
    for (int i = tid * 4; i < EKE; i += 1024)
        *(float4*)(se + i) = *(const float4*)(esrc + i);
    __syncthreads();

    int wi = tid >> 5, lane = tid & 31;
    for (int row = wi; row < NROW; row += 8) {
        const float* dxr = g_dx + (size_t)row * DXSTR + base;
        float p = 0.f;
        for (int q = lane * 4; q < qmax; q += 128) {
            float4 d = *(const float4*)(dxr + q);
            float4 ev = *(const float4*)(se + q);
            p = fmaf(d.x, ev.x, fmaf(d.y, ev.y, fmaf(d.z, ev.z, fmaf(d.w, ev.w, p))));
        }
        #pragma unroll
        for (int o = 16; o > 0; o >>= 1) p += __shfl_xor_sync(0xffffffffu, p, o);
        if (lane == 0) g_tmpA[(sc * NROW + row) * OUTW + wE] = p;
    }
}

// ---------------- resize stage B: scale axis 128 -> 224 ----------------
__global__ void k_resize_h(float* __restrict__ out) {
    int idx = blockIdx.x * blockDim.x + threadIdx.x;
    if (idx >= OUTN) return;
    int c = idx % Cn;
    int w = (idx / Cn) % OUTW;
    int h = (idx / (Cn * OUTW)) % OUTH;
    int b = idx / (Cn * OUTW * OUTH);
    int i0 = g_whi[h * 2 + 0], i1 = g_whi[h * 2 + 1];
    float f0 = g_whw[h * 2 + 0], f1 = g_whw[h * 2 + 1];
    int rb = (c * Bn + b) * OUTW + w;
    out[idx] = f0 * g_tmpA[i0 * NROW * OUTW + rb] + f1 * g_tmpA[i1 * NROW * OUTW + rb];
}

// ---------------- launch ----------------
extern "C" void kernel_launch(void* const* d_in, const int* in_sizes, int n_in,
                              void* d_out, int out_size) {
    const float* x   = (const float*)d_in[0];       // (32, 4096, 3) f32
    const float* psi = (const float*)d_in[1];       // (4096,) f32
    float* out = (float*)d_out;

    k_setup<<<1, 256>>>();
    k_dx<<<(NROW * DXSTR + 255) / 256, 256>>>(x);
    k_ebuildT<<<dim3(9, NSC), 256>>>(psi);
    k_gemm<<<dim3(48, 7), 128>>>();                  // launch #3 -> ncu captures this
    k_fixup<<<dim3(2, NSC), 256>>>();
    k_resize_h<<<(OUTN + 255) / 256, 256>>>(out);
}

// round 7
// speedup vs baseline: 5.1174x; 1.2608x over previous
#include <cuda_runtime.h>
#include <math.h>

// ---------------- static configuration ----------------
#define Bn     32
#define Tn     4096
#define Cn     3
#define NSC    128
#define NPSI   4096
#define PADL   2047
#define LP     8190           // Tn + 2*PADL
#define DXSTR  8192
#define NROW   96             // Cn * Bn
#define OUTH   224
#define OUTW   224
#define OUTN   (Bn*OUTH*OUTW*Cn)

#define U0     384            // global u-grid origin
#define KE     3456           // Ê u-extent
#define MTOT   896            // 128 scales x 7 interior classes
#define KMAX   3268           // >= max wavelet kernel length 3265
#define EKE    3328           // edge-kernel stride (fixup)

#define BM     128
#define BN     64
#define BK     16
#define SAST   132
#define SBST   68
#define KC     512            // split-K chunk
#define MAXCH  26             // grid.y over-provision (real ~19)
#define NTOTAL 3072           // 96 rows x 32 j

// ---------------- device scratch ----------------
__device__ __align__(16) float g_dx[NROW * DXSTR + 4096];      // 3 MB (zero-init)
__device__ __align__(16) float g_ehT[(size_t)KE * MTOT + 64];  // 12.4 MB  [u][m]
__device__ __align__(16) float g_eke[NSC * 2 * EKE];           // 3.4 MB edge kernels
__device__ __align__(16) float g_part[(size_t)MAXCH * BM * NTOTAL]; // 41 MB partials
__device__ float  g_tmpA[NSC * NROW * OUTW];                   // 11 MB
__device__ int    g_n[NSC];
__device__ int    g_d0[NSC];
__device__ float  g_nsq[NSC];
__device__ double g_sden[NSC];
__device__ float  g_wt[OUTW * 40];
__device__ int    g_wst[OUTW];
__device__ int    g_wcnt[OUTW];
__device__ int    g_whi[OUTH * 2];
__device__ float  g_whw[OUTH * 2];
__device__ int    g_tk[7 * 2];                                 // per-M-tile K window
__device__ int    g_chk[MAXCH * 2];                            // chunk -> (mt, klo)
__device__ int    g_chklen[MAXCH];
__device__ int    g_nchk;
__device__ int    g_tfirst[7];
__device__ int    g_tcnt[7];

// ---------------- setup: scales, resize weights, K windows, split-K chunks ----------------
__global__ void k_setup() {
    int tid = threadIdx.x;
    if (tid < NSC) {
        double l2 = log10(2.0), lM = log10(204.0);
        double y = (tid == NSC - 1) ? lM : (l2 + (double)tid * ((lM - l2) / (double)(NSC - 1)));
        float  sf = (float)pow(10.0, y);
        double sd = (double)sf;
        int n = (int)ceil(sd * 16.0 + 1.0);
        int d0 = (4094 - n) / 2; if (d0 < 0) d0 = 0;
        g_n[tid]   = n;
        g_d0[tid]  = d0;
        g_nsq[tid] = -sqrtf(sf);
        g_sden[tid] = sd * (16.0 / 4095.0);
    }
    if (tid < OUTW) {
        double inv = 4096.0 / 224.0;
        double ks  = inv;
        double sf  = ((double)tid + 0.5) * inv - 0.5;
        int lo = (int)ceil(sf - ks);  if (lo < 0) lo = 0;
        int hi = (int)floor(sf + ks); if (hi > Tn - 1) hi = Tn - 1;
        double tot = 0.0;
        for (int i = lo; i <= hi; i++) {
            double w = 1.0 - fabs((double)i - sf) / ks; if (w < 0.0) w = 0.0;
            tot += w;
        }
        int cnt = hi - lo + 1;
        g_wst[tid] = lo; g_wcnt[tid] = cnt;
        for (int j = 0; j < cnt; j++) {
            double w = 1.0 - fabs((double)(lo + j) - sf) / ks; if (w < 0.0) w = 0.0;
            g_wt[tid * 40 + j] = (float)(w / tot);
        }
        for (int j = cnt; j < 40; j++) g_wt[tid * 40 + j] = 0.0f;
    }
    if (tid < OUTH) {
        double inv = 128.0 / 224.0;
        double sf  = ((double)tid + 0.5) * inv - 0.5;
        int ia = (int)floor(sf);
        int i0 = ia, i1 = ia + 1;
        double w0 = 1.0 - (sf - (double)ia);
        double w1 = sf - (double)ia;
        bool v0 = (i0 >= 0 && i0 < NSC);
        bool v1 = (i1 >= 0 && i1 < NSC);
        double tot = (v0 ? w0 : 0.0) + (v1 ? w1 : 0.0);
        int   o0 = v0 ? i0 : (v1 ? i1 : 0);
        int   o1 = v1 ? i1 : (v0 ? i0 : 0);
        float f0 = v0 ? (float)(w0 / tot) : 0.0f;
        float f1 = v1 ? (float)(w1 / tot) : 0.0f;
        if (!v0 && v1) { f0 = (float)(w1 / tot); f1 = 0.0f; }
        g_whi[tid * 2 + 0] = o0; g_whi[tid * 2 + 1] = o1;
        g_whw[tid * 2 + 0] = f0; g_whw[tid * 2 + 1] = f1;
    }
    __syncthreads();
    if (tid < 7) {
        int smin = (BM * tid) / 7;
        int smax = (BM * tid + BM - 1) / 7; if (smax > NSC - 1) smax = NSC - 1;
        int lo = 1 << 30, hi = 0;
        for (int s = smin; s <= smax; s++) {
            for (int c = 0; c < 7; c++) {
                int A = g_d0[s] + g_wst[7 + c] - 128;
                int e = A + g_n[s] + g_wcnt[7 + c] - 1;
                int a0 = A - U0, e0 = e + 1 - U0;
                if (a0 < lo) lo = a0;
                if (e0 > hi) hi = e0;
            }
        }
        g_tk[tid * 2 + 0] = lo & ~15;
        g_tk[tid * 2 + 1] = (hi + 15) & ~15;
    }
    __syncthreads();
    if (tid == 0) {
        int nc = 0;
        for (int q = 0; q < 7; q++) {
            int mt = 6 - q;                       // heavy tiles first
            int klo = g_tk[mt * 2], khi = g_tk[mt * 2 + 1];
            g_tfirst[mt] = nc;
            int cnt = 0;
            for (int k = klo; k < khi && nc < MAXCH; k += KC) {
                int len = khi - k; if (len > KC) len = KC;
                g_chk[nc * 2 + 0] = mt;
                g_chk[nc * 2 + 1] = k;
                g_chklen[nc] = len;
                nc++; cnt++;
            }
            g_tcnt[mt] = cnt;
        }
        g_nchk = nc;
    }
}

// ---------------- dx = diff(reflect_pad(x)) ----------------
__device__ __forceinline__ float xp_val(const float* __restrict__ x, int b, int c, int p) {
    int i = p - PADL;
    if (i < 0) i = -i;
    else if (i >= Tn) i = 2 * (Tn - 1) - i;
    return x[((size_t)b * Tn + i) * Cn + c];
}

__global__ void k_dx(const float* __restrict__ x) {
    int idx = blockIdx.x * blockDim.x + threadIdx.x;
    if (idx >= NROW * DXSTR) return;
    int r = idx >> 13;
    int p = idx & (DXSTR - 1);
    int c = r / Bn, b = r % Bn;
    float v = 0.0f;
    if (p <= LP - 2) v = xp_val(x, b, c, p + 1) - xp_val(x, b, c, p);
    g_dx[idx] = v;
}

// ---------------- build resize-folded kernels ----------------
__global__ __launch_bounds__(256) void k_ebuildT(const float* __restrict__ psi) {
    __shared__ float skern[KMAX];
    __shared__ float swt[40];
    int cls = blockIdx.x;
    int sc  = blockIdx.y;
    int tid = threadIdx.x;
    int n = g_n[sc], d0 = g_d0[sc];
    double den = g_sden[sc];
    float nsq = g_nsq[sc];
    int wrep = (cls < 7) ? (7 + cls) : ((cls == 7) ? 0 : 223);
    int st = g_wst[wrep], cnt = g_wcnt[wrep];

    for (int k = tid; k < n; k += 256) {
        int m = n - 1 - k;                                  // flip
        int j = (int)floor((double)m / den);
        if (j < 0) j = 0;
        if (j > NPSI - 1) j = NPSI - 1;
        skern[k] = psi[j];
    }
    if (tid < 40) swt[tid] = g_wt[wrep * 40 + tid];
    __syncthreads();

    int len = n + cnt - 1;
    if (cls < 7) {
        int A = d0 + st - 128;
        int m = sc * 7 + cls;
        int p0 = A - U0;
        for (int v = tid; v < KE; v += 256) {
            int p = v - p0;
            float acc = 0.0f;
            if (p >= 0 && p < len) {
                int t0 = p - (n - 1); if (t0 < 0) t0 = 0;
                int t1 = p; if (t1 > cnt - 1) t1 = cnt - 1;
                for (int t = t0; t <= t1; t++) acc += swt[t] * skern[p - t];
                acc *= nsq;
            }
            g_ehT[(size_t)v * MTOT + m] = acc;
        }
    } else {
        int sh = (d0 + st) & 3;
        float* dst = g_eke + (size_t)(sc * 2 + (cls - 7)) * EKE;
        for (int v = tid; v < EKE; v += 256) {
            int p = v - sh;
            float acc = 0.0f;
            if (p >= 0 && p < len) {
                int t0 = p - (n - 1); if (t0 < 0) t0 = 0;
                int t1 = p; if (t1 > cnt - 1) t1 = cnt - 1;
                for (int t = t0; t <= t1; t++) acc += swt[t] * skern[p - t];
                acc *= nsq;
            }
            dst[v] = acc;
        }
    }
}

// ---------------- main GEMM (split-K, partials) ----------------
__global__ __launch_bounds__(128, 4) void k_gemm() {
    int chunk = blockIdx.y;
    if (chunk >= g_nchk) return;
    int mt  = g_chk[chunk * 2 + 0];
    int klo = g_chk[chunk * 2 + 1];
    int nk  = g_chklen[chunk] >> 4;

    __shared__ float sA[2][BK][SAST];
    __shared__ float sB[2][BK][SBST];

    int nt = blockIdx.x;
    int m0 = mt * BM, n0 = nt * BN;
    int tid = threadIdx.x;
    int warp = tid >> 5, lane = tid & 31;
    int wm = warp >> 1, wn = warp & 1;
    int lm = lane >> 2, ln = lane & 3;
    int m8 = wm * 64 + lm * 8;
    int n8 = wn * 32 + ln * 8;

    int mq = tid & 31, kA = tid >> 5;
    int nb = tid & 63, kh = tid >> 6;
    int ng = n0 + nb; int brow = ng >> 5, bj = ng & 31;

    const float* pA = g_ehT + (size_t)(klo + kA) * MTOT + m0 + mq * 4;
    const float* pB = g_dx + (size_t)brow * DXSTR + U0 + klo + (bj << 7) + kh * 8;

    float4 Ar0, Ar1, Ar2, Ar3, Br0, Br1;
    Ar0 = *(const float4*)(pA);
    Ar1 = *(const float4*)(pA + (size_t)4 * MTOT);
    Ar2 = *(const float4*)(pA + (size_t)8 * MTOT);
    Ar3 = *(const float4*)(pA + (size_t)12 * MTOT);
    Br0 = *(const float4*)(pB);
    Br1 = *(const float4*)(pB + 4);
    {
        *(float4*)&sA[0][kA][mq * 4]      = Ar0;
        *(float4*)&sA[0][kA + 4][mq * 4]  = Ar1;
        *(float4*)&sA[0][kA + 8][mq * 4]  = Ar2;
        *(float4*)&sA[0][kA + 12][mq * 4] = Ar3;
        int k0 = kh * 8;
        sB[0][k0 + 0][nb] = Br0.x; sB[0][k0 + 1][nb] = Br0.y;
        sB[0][k0 + 2][nb] = Br0.z; sB[0][k0 + 3][nb] = Br0.w;
        sB[0][k0 + 4][nb] = Br1.x; sB[0][k0 + 5][nb] = Br1.y;
        sB[0][k0 + 6][nb] = Br1.z; sB[0][k0 + 7][nb] = Br1.w;
    }
    __syncthreads();

    float acc[8][8];
    #pragma unroll
    for (int i = 0; i < 8; i++)
        #pragma unroll
        for (int j = 0; j < 8; j++) acc[i][j] = 0.f;

    for (int kb = 0; kb < nk; kb++) {
        int cur = kb & 1;
        if (kb + 1 < nk) {
            const float* qA = pA + (size_t)(kb + 1) * BK * MTOT;
            const float* qB = pB + (kb + 1) * BK;
            Ar0 = *(const float4*)(qA);
            Ar1 = *(const float4*)(qA + (size_t)4 * MTOT);
            Ar2 = *(const float4*)(qA + (size_t)8 * MTOT);
            Ar3 = *(const float4*)(qA + (size_t)12 * MTOT);
            Br0 = *(const float4*)(qB);
            Br1 = *(const float4*)(qB + 4);
        }
        #pragma unroll
        for (int k = 0; k < BK; k++) {
            float a[8], b[8];
            *(float4*)(a)     = *(const float4*)&sA[cur][k][m8];
            *(float4*)(a + 4) = *(const float4*)&sA[cur][k][m8 + 4];
            *(float4*)(b)     = *(const float4*)&sB[cur][k][n8];
            *(float4*)(b + 4) = *(const float4*)&sB[cur][k][n8 + 4];
            #pragma unroll
            for (int i = 0; i < 8; i++)
                #pragma unroll
                for (int j = 0; j < 8; j++)
                    acc[i][j] = fmaf(a[i], b[j], acc[i][j]);
        }
        if (kb + 1 < nk) {
            int nx = cur ^ 1;
            *(float4*)&sA[nx][kA][mq * 4]      = Ar0;
            *(float4*)&sA[nx][kA + 4][mq * 4]  = Ar1;
            *(float4*)&sA[nx][kA + 8][mq * 4]  = Ar2;
            *(float4*)&sA[nx][kA + 12][mq * 4] = Ar3;
            int k0 = kh * 8;
            sB[nx][k0 + 0][nb] = Br0.x; sB[nx][k0 + 1][nb] = Br0.y;
            sB[nx][k0 + 2][nb] = Br0.z; sB[nx][k0 + 3][nb] = Br0.w;
            sB[nx][k0 + 4][nb] = Br1.x; sB[nx][k0 + 5][nb] = Br1.y;
            sB[nx][k0 + 6][nb] = Br1.z; sB[nx][k0 + 7][nb] = Br1.w;
        }
        __syncthreads();
    }

    // write partial tile (coalesced float4 in n)
    float* pp = g_part + ((size_t)chunk * BM) * NTOTAL;
    #pragma unroll
    for (int i = 0; i < 8; i++) {
        float* row = pp + (size_t)(m8 + i) * NTOTAL + n0 + n8;
        float4 v0 = make_float4(acc[i][0], acc[i][1], acc[i][2], acc[i][3]);
        float4 v1 = make_float4(acc[i][4], acc[i][5], acc[i][6], acc[i][7]);
        *(float4*)(row)     = v0;
        *(float4*)(row + 4) = v1;
    }
}

// ---------------- split-K reduction + scatter into g_tmpA ----------------
__global__ __launch_bounds__(256) void k_red() {
    int idx = blockIdx.x * 256 + threadIdx.x;        // one float4 column group
    if (idx >= MTOT * (NTOTAL / 4)) return;
    int m = idx / (NTOTAL / 4);
    int q = idx - m * (NTOTAL / 4);
    int n = q * 4;
    int mt = m >> 7, ml = m & 127;
    int first = g_tfirst[mt], cnt = g_tcnt[mt];
    float4 s = make_float4(0.f, 0.f, 0.f, 0.f);
    for (int c = 0; c < cnt; c++) {
        const float4 v = *(const float4*)(g_part + ((size_t)(first + c) * BM + ml) * NTOTAL + n);
        s.x += v.x; s.y += v.y; s.z += v.z; s.w += v.w;
    }
    int sc = m / 7, cc = m - sc * 7;
    int row = n >> 5, jj = n & 31;
    float* o = g_tmpA + (sc * NROW + row) * OUTW + 7 * jj + cc;
    o[0]  = s.x;
    o[7]  = s.y;
    o[14] = s.z;
    o[21] = s.w;
}

// ---------------- exact fixup for clipped edge columns w=0, w=223 ----------------
__global__ void k_fixup() {
    __shared__ float se[EKE];
    int e  = blockIdx.x;
    int sc = blockIdx.y;
    int tid = threadIdx.x;
    int wE = e ? 223 : 0;
    int n = g_n[sc], d0 = g_d0[sc];
    int st = g_wst[wE], cnt = g_wcnt[wE];
    int base = (d0 + st) & ~3;
    int sh = (d0 + st) & 3;
    int qmax = sh + n + cnt - 1;

    const float* esrc = g_eke + (size_t)(sc * 2 + e) * EKE;
    for (int i = tid * 4; i < EKE; i += 1024)
        *(float4*)(se + i) = *(const float4*)(esrc + i);
    __syncthreads();

    int wi = tid >> 5, lane = tid & 31;
    for (int row = wi; row < NROW; row += 8) {
        const float* dxr = g_dx + (size_t)row * DXSTR + base;
        float p = 0.f;
        for (int q = lane * 4; q < qmax; q += 128) {
            float4 d = *(const float4*)(dxr + q);
            float4 ev = *(const float4*)(se + q);
            p = fmaf(d.x, ev.x, fmaf(d.y, ev.y, fmaf(d.z, ev.z, fmaf(d.w, ev.w, p))));
        }
        #pragma unroll
        for (int o = 16; o > 0; o >>= 1) p += __shfl_xor_sync(0xffffffffu, p, o);
        if (lane == 0) g_tmpA[(sc * NROW + row) * OUTW + wE] = p;
    }
}

// ---------------- resize stage B: scale axis 128 -> 224 ----------------
__global__ void k_resize_h(float* __restrict__ out) {
    int idx = blockIdx.x * blockDim.x + threadIdx.x;
    if (idx >= OUTN) return;
    int c = idx % Cn;
    int w = (idx / Cn) % OUTW;
    int h = (idx / (Cn * OUTW)) % OUTH;
    int b = idx / (Cn * OUTW * OUTH);
    int i0 = g_whi[h * 2 + 0], i1 = g_whi[h * 2 + 1];
    float f0 = g_whw[h * 2 + 0], f1 = g_whw[h * 2 + 1];
    int rb = (c * Bn + b) * OUTW + w;
    out[idx] = f0 * g_tmpA[i0 * NROW * OUTW + rb] + f1 * g_tmpA[i1 * NROW * OUTW + rb];
}

// ---------------- launch ----------------
extern "C" void kernel_launch(void* const* d_in, const int* in_sizes, int n_in,
                              void* d_out, int out_size) {
    const float* x   = (const float*)d_in[0];       // (32, 4096, 3) f32
    const float* psi = (const float*)d_in[1];       // (4096,) f32
    float* out = (float*)d_out;

    k_setup<<<1, 256>>>();
    k_dx<<<(NROW * DXSTR + 255) / 256, 256>>>(x);
    k_ebuildT<<<dim3(9, NSC), 256>>>(psi);
    k_gemm<<<dim3(48, MAXCH), 128>>>();              // launch #3 -> ncu captures this
    k_red<<<(MTOT * (NTOTAL / 4) + 255) / 256, 256>>>();
    k_fixup<<<dim3(2, NSC), 256>>>();
    k_resize_h<<<(OUTN + 255) / 256, 256>>>(out);
}

// round 8
// speedup vs baseline: 5.2602x; 1.0279x over previous
#include <cuda_runtime.h>
#include <math.h>

// ---------------- static configuration ----------------
#define Bn     32
#define Tn     4096
#define Cn     3
#define NSC    128
#define NPSI   4096
#define PADL   2047
#define LP     8190           // Tn + 2*PADL
#define DXSTR  8192
#define NROW   96             // Cn * Bn
#define OUTH   224
#define OUTW   224
#define OUTN   (Bn*OUTH*OUTW*Cn)

#define U0     384            // global u-grid origin
#define KE     3456           // Ê u-extent
#define MTOT   896            // 128 scales x 7 interior classes
#define KMAX   3268           // >= max wavelet kernel length 3265
#define EKE    3328           // edge-kernel stride (fixup)

#define BM     128
#define BN     64
#define BK     16
#define SAST   132
#define SBST   68
#define KC     512            // split-K chunk
#define MAXCH  26             // grid.y over-provision (real ~19)
#define NTOTAL 3072           // 96 rows x 32 j

// ---------------- device scratch ----------------
__device__ __align__(16) float g_dx[NROW * DXSTR + 4096];      // 3 MB (zero-init)
__device__ __align__(16) float g_eh[(size_t)MTOT * KE + 64];   // 12.4 MB [m][k]
__device__ __align__(16) float g_ehT[(size_t)KE * MTOT + 64];  // 12.4 MB [k][m]
__device__ __align__(16) float g_eke[NSC * 2 * EKE];           // 3.4 MB edge kernels
__device__ __align__(16) float g_part[(size_t)MAXCH * BM * NTOTAL]; // 41 MB partials
__device__ float  g_tmpA[NSC * NROW * OUTW];                   // 11 MB
__device__ int    g_n[NSC];
__device__ int    g_d0[NSC];
__device__ float  g_nsq[NSC];
__device__ double g_sden[NSC];
__device__ float  g_wt[OUTW * 40];
__device__ int    g_wst[OUTW];
__device__ int    g_wcnt[OUTW];
__device__ int    g_whi[OUTH * 2];
__device__ float  g_whw[OUTH * 2];
__device__ int    g_tk[7 * 2];                                 // per-M-tile K window
__device__ int    g_chk[MAXCH * 2];                            // chunk -> (mt, klo)
__device__ int    g_chklen[MAXCH];
__device__ int    g_nchk;
__device__ int    g_tfirst[7];
__device__ int    g_tcnt[7];

// ---------------- setup ----------------
__global__ void k_setup() {
    int tid = threadIdx.x;
    if (tid < NSC) {
        double l2 = log10(2.0), lM = log10(204.0);
        double y = (tid == NSC - 1) ? lM : (l2 + (double)tid * ((lM - l2) / (double)(NSC - 1)));
        float  sf = (float)pow(10.0, y);
        double sd = (double)sf;
        int n = (int)ceil(sd * 16.0 + 1.0);
        int d0 = (4094 - n) / 2; if (d0 < 0) d0 = 0;
        g_n[tid]   = n;
        g_d0[tid]  = d0;
        g_nsq[tid] = -sqrtf(sf);
        g_sden[tid] = sd * (16.0 / 4095.0);
    }
    if (tid < OUTW) {
        double inv = 4096.0 / 224.0;
        double ks  = inv;
        double sf  = ((double)tid + 0.5) * inv - 0.5;
        int lo = (int)ceil(sf - ks);  if (lo < 0) lo = 0;
        int hi = (int)floor(sf + ks); if (hi > Tn - 1) hi = Tn - 1;
        double tot = 0.0;
        for (int i = lo; i <= hi; i++) {
            double w = 1.0 - fabs((double)i - sf) / ks; if (w < 0.0) w = 0.0;
            tot += w;
        }
        int cnt = hi - lo + 1;
        g_wst[tid] = lo; g_wcnt[tid] = cnt;
        for (int j = 0; j < cnt; j++) {
            double w = 1.0 - fabs((double)(lo + j) - sf) / ks; if (w < 0.0) w = 0.0;
            g_wt[tid * 40 + j] = (float)(w / tot);
        }
        for (int j = cnt; j < 40; j++) g_wt[tid * 40 + j] = 0.0f;
    }
    if (tid < OUTH) {
        double inv = 128.0 / 224.0;
        double sf  = ((double)tid + 0.5) * inv - 0.5;
        int ia = (int)floor(sf);
        int i0 = ia, i1 = ia + 1;
        double w0 = 1.0 - (sf - (double)ia);
        double w1 = sf - (double)ia;
        bool v0 = (i0 >= 0 && i0 < NSC);
        bool v1 = (i1 >= 0 && i1 < NSC);
        double tot = (v0 ? w0 : 0.0) + (v1 ? w1 : 0.0);
        int   o0 = v0 ? i0 : (v1 ? i1 : 0);
        int   o1 = v1 ? i1 : (v0 ? i0 : 0);
        float f0 = v0 ? (float)(w0 / tot) : 0.0f;
        float f1 = v1 ? (float)(w1 / tot) : 0.0f;
        if (!v0 && v1) { f0 = (float)(w1 / tot); f1 = 0.0f; }
        g_whi[tid * 2 + 0] = o0; g_whi[tid * 2 + 1] = o1;
        g_whw[tid * 2 + 0] = f0; g_whw[tid * 2 + 1] = f1;
    }
    __syncthreads();
    if (tid < 7) {
        int smin = (BM * tid) / 7;
        int smax = (BM * tid + BM - 1) / 7; if (smax > NSC - 1) smax = NSC - 1;
        int lo = 1 << 30, hi = 0;
        for (int s = smin; s <= smax; s++) {
            for (int c = 0; c < 7; c++) {
                int A = g_d0[s] + g_wst[7 + c] - 128;
                int e = A + g_n[s] + g_wcnt[7 + c] - 1;
                int a0 = A - U0, e0 = e + 1 - U0;
                if (a0 < lo) lo = a0;
                if (e0 > hi) hi = e0;
            }
        }
        g_tk[tid * 2 + 0] = lo & ~15;
        g_tk[tid * 2 + 1] = (hi + 15) & ~15;
    }
    __syncthreads();
    if (tid == 0) {
        int nc = 0;
        for (int q = 0; q < 7; q++) {
            int mt = 6 - q;                       // heavy tiles first
            int klo = g_tk[mt * 2], khi = g_tk[mt * 2 + 1];
            g_tfirst[mt] = nc;
            int cnt = 0;
            for (int k = klo; k < khi && nc < MAXCH; k += KC) {
                int len = khi - k; if (len > KC) len = KC;
                g_chk[nc * 2 + 0] = mt;
                g_chk[nc * 2 + 1] = k;
                g_chklen[nc] = len;
                nc++; cnt++;
            }
            g_tcnt[mt] = cnt;
        }
        g_nchk = nc;
    }
}

// ---------------- dx = diff(reflect_pad(x)) ----------------
__device__ __forceinline__ float xp_val(const float* __restrict__ x, int b, int c, int p) {
    int i = p - PADL;
    if (i < 0) i = -i;
    else if (i >= Tn) i = 2 * (Tn - 1) - i;
    return x[((size_t)b * Tn + i) * Cn + c];
}

__global__ void k_dx(const float* __restrict__ x) {
    int idx = blockIdx.x * blockDim.x + threadIdx.x;
    if (idx >= NROW * DXSTR) return;
    int r = idx >> 13;
    int p = idx & (DXSTR - 1);
    int c = r / Bn, b = r % Bn;
    float v = 0.0f;
    if (p <= LP - 2) v = xp_val(x, b, c, p + 1) - xp_val(x, b, c, p);
    g_dx[idx] = v;
}

// ---------------- build resize-folded kernels (m-major, coalesced) ----------------
__global__ __launch_bounds__(256) void k_ebuild(const float* __restrict__ psi) {
    __shared__ float skern[KMAX];
    __shared__ float swt[40];
    int cls = blockIdx.x;
    int sc  = blockIdx.y;
    int tid = threadIdx.x;
    int n = g_n[sc], d0 = g_d0[sc];
    double den = g_sden[sc];
    float nsq = g_nsq[sc];
    int wrep = (cls < 7) ? (7 + cls) : ((cls == 7) ? 0 : 223);
    int st = g_wst[wrep], cnt = g_wcnt[wrep];

    for (int k = tid; k < n; k += 256) {
        int m = n - 1 - k;                                  // flip
        int j = (int)floor((double)m / den);
        if (j < 0) j = 0;
        if (j > NPSI - 1) j = NPSI - 1;
        skern[k] = psi[j];
    }
    if (tid < 40) swt[tid] = g_wt[wrep * 40 + tid];
    __syncthreads();

    int len = n + cnt - 1;
    if (cls < 7) {
        int A = d0 + st - 128;
        int m = sc * 7 + cls;
        int p0 = A - U0;
        float* dst = g_eh + (size_t)m * KE;
        for (int v = tid; v < KE; v += 256) {
            int p = v - p0;
            float acc = 0.0f;
            if (p >= 0 && p < len) {
                int t0 = p - (n - 1); if (t0 < 0) t0 = 0;
                int t1 = p; if (t1 > cnt - 1) t1 = cnt - 1;
                for (int t = t0; t <= t1; t++) acc += swt[t] * skern[p - t];
                acc *= nsq;
            }
            dst[v] = acc;
        }
    } else {
        int sh = (d0 + st) & 3;
        float* dst = g_eke + (size_t)(sc * 2 + (cls - 7)) * EKE;
        for (int v = tid; v < EKE; v += 256) {
            int p = v - sh;
            float acc = 0.0f;
            if (p >= 0 && p < len) {
                int t0 = p - (n - 1); if (t0 < 0) t0 = 0;
                int t1 = p; if (t1 > cnt - 1) t1 = cnt - 1;
                for (int t = t0; t <= t1; t++) acc += swt[t] * skern[p - t];
                acc *= nsq;
            }
            dst[v] = acc;
        }
    }
}

// ---------------- transpose g_eh [m][k] -> g_ehT [k][m] ----------------
__global__ __launch_bounds__(256) void k_trans() {
    __shared__ float t[32][33];
    int k0 = blockIdx.x * 32;
    int m0 = blockIdx.y * 32;
    int tx = threadIdx.x & 31;
    int ty = threadIdx.x >> 5;       // 0..7
    #pragma unroll
    for (int r = 0; r < 4; r++) {
        int m = m0 + ty + r * 8;
        t[ty + r * 8][tx] = g_eh[(size_t)m * KE + k0 + tx];
    }
    __syncthreads();
    #pragma unroll
    for (int r = 0; r < 4; r++) {
        int k = k0 + ty + r * 8;
        g_ehT[(size_t)k * MTOT + m0 + tx] = t[tx][ty + r * 8];
    }
}

// ---------------- main GEMM (split-K, partials) ----------------
__global__ __launch_bounds__(128, 4) void k_gemm() {
    int chunk = blockIdx.y;
    if (chunk >= g_nchk) return;
    int mt  = g_chk[chunk * 2 + 0];
    int klo = g_chk[chunk * 2 + 1];
    int nk  = g_chklen[chunk] >> 4;

    __shared__ float sA[2][BK][SAST];
    __shared__ float sB[2][BK][SBST];

    int nt = blockIdx.x;
    int m0 = mt * BM, n0 = nt * BN;
    int tid = threadIdx.x;
    int warp = tid >> 5, lane = tid & 31;
    int wm = warp >> 1, wn = warp & 1;
    int lm = lane >> 2, ln = lane & 3;
    int m8 = wm * 64 + lm * 8;
    int n8 = wn * 32 + ln * 8;

    int mq = tid & 31, kA = tid >> 5;
    int nb = tid & 63, kh = tid >> 6;
    int ng = n0 + nb; int brow = ng >> 5, bj = ng & 31;

    const float* pA = g_ehT + (size_t)(klo + kA) * MTOT + m0 + mq * 4;
    const float* pB = g_dx + (size_t)brow * DXSTR + U0 + klo + (bj << 7) + kh * 8;

    float4 Ar0, Ar1, Ar2, Ar3, Br0, Br1;
    Ar0 = *(const float4*)(pA);
    Ar1 = *(const float4*)(pA + (size_t)4 * MTOT);
    Ar2 = *(const float4*)(pA + (size_t)8 * MTOT);
    Ar3 = *(const float4*)(pA + (size_t)12 * MTOT);
    Br0 = *(const float4*)(pB);
    Br1 = *(const float4*)(pB + 4);
    {
        *(float4*)&sA[0][kA][mq * 4]      = Ar0;
        *(float4*)&sA[0][kA + 4][mq * 4]  = Ar1;
        *(float4*)&sA[0][kA + 8][mq * 4]  = Ar2;
        *(float4*)&sA[0][kA + 12][mq * 4] = Ar3;
        int k0 = kh * 8;
        sB[0][k0 + 0][nb] = Br0.x; sB[0][k0 + 1][nb] = Br0.y;
        sB[0][k0 + 2][nb] = Br0.z; sB[0][k0 + 3][nb] = Br0.w;
        sB[0][k0 + 4][nb] = Br1.x; sB[0][k0 + 5][nb] = Br1.y;
        sB[0][k0 + 6][nb] = Br1.z; sB[0][k0 + 7][nb] = Br1.w;
    }
    __syncthreads();

    float acc[8][8];
    #pragma unroll
    for (int i = 0; i < 8; i++)
        #pragma unroll
        for (int j = 0; j < 8; j++) acc[i][j] = 0.f;

    for (int kb = 0; kb < nk; kb++) {
        int cur = kb & 1;
        if (kb + 1 < nk) {
            const float* qA = pA + (size_t)(kb + 1) * BK * MTOT;
            const float* qB = pB + (kb + 1) * BK;
            Ar0 = *(const float4*)(qA);
            Ar1 = *(const float4*)(qA + (size_t)4 * MTOT);
            Ar2 = *(const float4*)(qA + (size_t)8 * MTOT);
            Ar3 = *(const float4*)(qA + (size_t)12 * MTOT);
            Br0 = *(const float4*)(qB);
            Br1 = *(const float4*)(qB + 4);
        }
        #pragma unroll
        for (int k = 0; k < BK; k++) {
            float a[8], b[8];
            *(float4*)(a)     = *(const float4*)&sA[cur][k][m8];
            *(float4*)(a + 4) = *(const float4*)&sA[cur][k][m8 + 4];
            *(float4*)(b)     = *(const float4*)&sB[cur][k][n8];
            *(float4*)(b + 4) = *(const float4*)&sB[cur][k][n8 + 4];
            #pragma unroll
            for (int i = 0; i < 8; i++)
                #pragma unroll
                for (int j = 0; j < 8; j++)
                    acc[i][j] = fmaf(a[i], b[j], acc[i][j]);
        }
        if (kb + 1 < nk) {
            int nx = cur ^ 1;
            *(float4*)&sA[nx][kA][mq * 4]      = Ar0;
            *(float4*)&sA[nx][kA + 4][mq * 4]  = Ar1;
            *(float4*)&sA[nx][kA + 8][mq * 4]  = Ar2;
            *(float4*)&sA[nx][kA + 12][mq * 4] = Ar3;
            int k0 = kh * 8;
            sB[nx][k0 + 0][nb] = Br0.x; sB[nx][k0 + 1][nb] = Br0.y;
            sB[nx][k0 + 2][nb] = Br0.z; sB[nx][k0 + 3][nb] = Br0.w;
            sB[nx][k0 + 4][nb] = Br1.x; sB[nx][k0 + 5][nb] = Br1.y;
            sB[nx][k0 + 6][nb] = Br1.z; sB[nx][k0 + 7][nb] = Br1.w;
        }
        __syncthreads();
    }

    float* pp = g_part + ((size_t)chunk * BM) * NTOTAL;
    #pragma unroll
    for (int i = 0; i < 8; i++) {
        float* row = pp + (size_t)(m8 + i) * NTOTAL + n0 + n8;
        float4 v0 = make_float4(acc[i][0], acc[i][1], acc[i][2], acc[i][3]);
        float4 v1 = make_float4(acc[i][4], acc[i][5], acc[i][6], acc[i][7]);
        *(float4*)(row)     = v0;
        *(float4*)(row + 4) = v1;
    }
}

// ---------------- split-K reduction + scatter into g_tmpA ----------------
__global__ __launch_bounds__(256) void k_red() {
    int idx = blockIdx.x * 256 + threadIdx.x;
    if (idx >= MTOT * (NTOTAL / 4)) return;
    int m = idx / (NTOTAL / 4);
    int q = idx - m * (NTOTAL / 4);
    int n = q * 4;
    int mt = m >> 7, ml = m & 127;
    int first = g_tfirst[mt], cnt = g_tcnt[mt];
    float4 s = make_float4(0.f, 0.f, 0.f, 0.f);
    for (int c = 0; c < cnt; c++) {
        const float4 v = *(const float4*)(g_part + ((size_t)(first + c) * BM + ml) * NTOTAL + n);
        s.x += v.x; s.y += v.y; s.z += v.z; s.w += v.w;
    }
    int sc = m / 7, cc = m - sc * 7;
    int row = n >> 5, jj = n & 31;
    float* o = g_tmpA + (sc * NROW + row) * OUTW + 7 * jj + cc;
    o[0]  = s.x;
    o[7]  = s.y;
    o[14] = s.z;
    o[21] = s.w;
}

// ---------------- exact fixup for clipped edge columns w=0, w=223 ----------------
__global__ void k_fixup() {
    __shared__ float se[EKE];
    int e  = blockIdx.x;
    int sc = blockIdx.y;
    int tid = threadIdx.x;
    int wE = e ? 223 : 0;
    int n = g_n[sc], d0 = g_d0[sc];
    int st = g_wst[wE], cnt = g_wcnt[wE];
    int base = (d0 + st) & ~3;
    int sh = (d0 + st) & 3;
    int qmax = sh + n + cnt - 1;

    const float* esrc = g_eke + (size_t)(sc * 2 + e) * EKE;
    for (int i = tid * 4; i < EKE; i += 1024)
        *(float4*)(se + i) = *(const float4*)(esrc + i);
    __syncthreads();

    int wi = tid >> 5, lane = tid & 31;
    for (int row = wi; row < NROW; row += 8) {
        const float* dxr = g_dx + (size_t)row * DXSTR + base;
        float p = 0.f;
        for (int q = lane * 4; q < qmax; q += 128) {
            float4 d = *(const float4*)(dxr + q);
            float4 ev = *(const float4*)(se + q);
            p = fmaf(d.x, ev.x, fmaf(d.y, ev.y, fmaf(d.z, ev.z, fmaf(d.w, ev.w, p))));
        }
        #pragma unroll
        for (int o = 16; o > 0; o >>= 1) p += __shfl_xor_sync(0xffffffffu, p, o);
        if (lane == 0) g_tmpA[(sc * NROW + row) * OUTW + wE] = p;
    }
}

// ---------------- resize stage B: scale axis 128 -> 224 ----------------
__global__ void k_resize_h(float* __restrict__ out) {
    int idx = blockIdx.x * blockDim.x + threadIdx.x;
    if (idx >= OUTN) return;
    int c = idx % Cn;
    int w = (idx / Cn) % OUTW;
    int h = (idx / (Cn * OUTW)) % OUTH;
    int b = idx / (Cn * OUTW * OUTH);
    int i0 = g_whi[h * 2 + 0], i1 = g_whi[h * 2 + 1];
    float f0 = g_whw[h * 2 + 0], f1 = g_whw[h * 2 + 1];
    int rb = (c * Bn + b) * OUTW + w;
    out[idx] = f0 * g_tmpA[i0 * NROW * OUTW + rb] + f1 * g_tmpA[i1 * NROW * OUTW + rb];
}

// ---------------- launch ----------------
extern "C" void kernel_launch(void* const* d_in, const int* in_sizes, int n_in,
                              void* d_out, int out_size) {
    const float* x   = (const float*)d_in[0];       // (32, 4096, 3) f32
    const float* psi = (const float*)d_in[1];       // (4096,) f32
    float* out = (float*)d_out;

    k_setup<<<1, 256>>>();
    k_dx<<<(NROW * DXSTR + 255) / 256, 256>>>(x);
    k_ebuild<<<dim3(9, NSC), 256>>>(psi);
    k_trans<<<dim3(KE / 32, MTOT / 32), 256>>>();
    k_gemm<<<dim3(48, MAXCH), 128>>>();
    k_red<<<(MTOT * (NTOTAL / 4) + 255) / 256, 256>>>();
    k_fixup<<<dim3(2, NSC), 256>>>();
    k_resize_h<<<(OUTN + 255) / 256, 256>>>(out);
}

// round 9
// speedup vs baseline: 5.4718x; 1.0402x over previous
#include <cuda_runtime.h>
#include <math.h>

// ---------------- static configuration ----------------
#define Bn     32
#define Tn     4096
#define Cn     3
#define NSC    128
#define NPSI   4096
#define PADL   2047
#define LP     8190           // Tn + 2*PADL
#define DXSTR  8192
#define NROW   96             // Cn * Bn
#define OUTH   224
#define OUTW   224
#define OUTN   (Bn*OUTH*OUTW*Cn)

#define U0     384            // global u-grid origin
#define KE     3456           // Ê u-extent
#define MTOT   896            // 128 scales x 7 interior classes
#define KMAX   3268           // >= max wavelet kernel length 3265
#define KSTR   3280           // g_kern row stride
#define EKE    3328           // edge-kernel stride (fixup)

#define BM     128
#define BN     64
#define BK     16
#define SAST   132
#define SBST   68
#define KC     512            // split-K chunk
#define MAXCH  26             // grid.y over-provision (real ~19)
#define NTOTAL 3072           // 96 rows x 32 j

// ---------------- device scratch ----------------
__device__ __align__(16) float g_dx[NROW * DXSTR + 4096];      // 3 MB (zero-init)
__device__ __align__(16) float g_kern[NSC * KSTR];             // 1.7 MB gathered kernels
__device__ __align__(16) float g_eh[(size_t)MTOT * KE + 64];   // 12.4 MB [m][k]
__device__ __align__(16) float g_ehT[(size_t)KE * MTOT + 64];  // 12.4 MB [k][m]
__device__ __align__(16) float g_eke[NSC * 2 * EKE];           // 3.4 MB edge kernels
__device__ __align__(16) float g_part[(size_t)MAXCH * BM * NTOTAL]; // 41 MB partials
__device__ __align__(16) float g_tmpB[(size_t)MTOT * NTOTAL];  // 11 MB [m][n] reduced
__device__ float  g_tmpA[NSC * NROW * OUTW];                   // 11 MB [sc][row][w]
__device__ int    g_n[NSC];
__device__ int    g_d0[NSC];
__device__ float  g_nsq[NSC];
__device__ double g_sden[NSC];
__device__ float  g_wt[OUTW * 40];
__device__ int    g_wst[OUTW];
__device__ int    g_wcnt[OUTW];
__device__ int    g_whi[OUTH * 2];
__device__ float  g_whw[OUTH * 2];
__device__ int    g_tk[7 * 2];                                 // per-M-tile K window
__device__ int    g_chk[MAXCH * 2];                            // chunk -> (mt, klo)
__device__ int    g_chklen[MAXCH];
__device__ int    g_nchk;
__device__ int    g_tfirst[7];
__device__ int    g_tcnt[7];

// ---------------- setup ----------------
__global__ void k_setup() {
    int tid = threadIdx.x;
    if (tid < NSC) {
        double l2 = log10(2.0), lM = log10(204.0);
        double y = (tid == NSC - 1) ? lM : (l2 + (double)tid * ((lM - l2) / (double)(NSC - 1)));
        float  sf = (float)pow(10.0, y);
        double sd = (double)sf;
        int n = (int)ceil(sd * 16.0 + 1.0);
        int d0 = (4094 - n) / 2; if (d0 < 0) d0 = 0;
        g_n[tid]   = n;
        g_d0[tid]  = d0;
        g_nsq[tid] = -sqrtf(sf);
        g_sden[tid] = sd * (16.0 / 4095.0);
    }
    if (tid < OUTW) {
        double inv = 4096.0 / 224.0;
        double ks  = inv;
        double sf  = ((double)tid + 0.5) * inv - 0.5;
        int lo = (int)ceil(sf - ks);  if (lo < 0) lo = 0;
        int hi = (int)floor(sf + ks); if (hi > Tn - 1) hi = Tn - 1;
        double tot = 0.0;
        for (int i = lo; i <= hi; i++) {
            double w = 1.0 - fabs((double)i - sf) / ks; if (w < 0.0) w = 0.0;
            tot += w;
        }
        int cnt = hi - lo + 1;
        g_wst[tid] = lo; g_wcnt[tid] = cnt;
        for (int j = 0; j < cnt; j++) {
            double w = 1.0 - fabs((double)(lo + j) - sf) / ks; if (w < 0.0) w = 0.0;
            g_wt[tid * 40 + j] = (float)(w / tot);
        }
        for (int j = cnt; j < 40; j++) g_wt[tid * 40 + j] = 0.0f;
    }
    if (tid < OUTH) {
        double inv = 128.0 / 224.0;
        double sf  = ((double)tid + 0.5) * inv - 0.5;
        int ia = (int)floor(sf);
        int i0 = ia, i1 = ia + 1;
        double w0 = 1.0 - (sf - (double)ia);
        double w1 = sf - (double)ia;
        bool v0 = (i0 >= 0 && i0 < NSC);
        bool v1 = (i1 >= 0 && i1 < NSC);
        double tot = (v0 ? w0 : 0.0) + (v1 ? w1 : 0.0);
        int   o0 = v0 ? i0 : (v1 ? i1 : 0);
        int   o1 = v1 ? i1 : (v0 ? i0 : 0);
        float f0 = v0 ? (float)(w0 / tot) : 0.0f;
        float f1 = v1 ? (float)(w1 / tot) : 0.0f;
        if (!v0 && v1) { f0 = (float)(w1 / tot); f1 = 0.0f; }
        g_whi[tid * 2 + 0] = o0; g_whi[tid * 2 + 1] = o1;
        g_whw[tid * 2 + 0] = f0; g_whw[tid * 2 + 1] = f1;
    }
    __syncthreads();
    if (tid < 7) {
        int smin = (BM * tid) / 7;
        int smax = (BM * tid + BM - 1) / 7; if (smax > NSC - 1) smax = NSC - 1;
        int lo = 1 << 30, hi = 0;
        for (int s = smin; s <= smax; s++) {
            for (int c = 0; c < 7; c++) {
                int A = g_d0[s] + g_wst[7 + c] - 128;
                int e = A + g_n[s] + g_wcnt[7 + c] - 1;
                int a0 = A - U0, e0 = e + 1 - U0;
                if (a0 < lo) lo = a0;
                if (e0 > hi) hi = e0;
            }
        }
        g_tk[tid * 2 + 0] = lo & ~15;
        g_tk[tid * 2 + 1] = (hi + 15) & ~15;
    }
    __syncthreads();
    if (tid == 0) {
        int nc = 0;
        for (int q = 0; q < 7; q++) {
            int mt = 6 - q;                       // heavy tiles first
            int klo = g_tk[mt * 2], khi = g_tk[mt * 2 + 1];
            g_tfirst[mt] = nc;
            int cnt = 0;
            for (int k = klo; k < khi && nc < MAXCH; k += KC) {
                int len = khi - k; if (len > KC) len = KC;
                g_chk[nc * 2 + 0] = mt;
                g_chk[nc * 2 + 1] = k;
                g_chklen[nc] = len;
                nc++; cnt++;
            }
            g_tcnt[mt] = cnt;
        }
        g_nchk = nc;
    }
}

// ---------------- gather flipped wavelet kernel once per scale ----------------
__global__ __launch_bounds__(256) void k_gather(const float* __restrict__ psi) {
    int sc = blockIdx.x;
    int n = g_n[sc];
    double den = g_sden[sc];
    for (int k = threadIdx.x; k < n; k += 256) {
        int m = n - 1 - k;                                  // flip
        int j = (int)floor((double)m / den);
        if (j < 0) j = 0;
        if (j > NPSI - 1) j = NPSI - 1;
        g_kern[sc * KSTR + k] = psi[j];
    }
}

// ---------------- dx = diff(reflect_pad(x)) ----------------
__device__ __forceinline__ float xp_val(const float* __restrict__ x, int b, int c, int p) {
    int i = p - PADL;
    if (i < 0) i = -i;
    else if (i >= Tn) i = 2 * (Tn - 1) - i;
    return x[((size_t)b * Tn + i) * Cn + c];
}

__global__ void k_dx(const float* __restrict__ x) {
    int idx = blockIdx.x * blockDim.x + threadIdx.x;
    if (idx >= NROW * DXSTR) return;
    int r = idx >> 13;
    int p = idx & (DXSTR - 1);
    int c = r / Bn, b = r % Bn;
    float v = 0.0f;
    if (p <= LP - 2) v = xp_val(x, b, c, p + 1) - xp_val(x, b, c, p);
    g_dx[idx] = v;
}

// ---------------- build resize-folded kernels (no divides, coalesced) ----------------
__global__ __launch_bounds__(256) void k_ebuild() {
    __shared__ float skern[KMAX];
    __shared__ float swt[40];
    int cls = blockIdx.x;
    int sc  = blockIdx.y;
    int tid = threadIdx.x;
    int n = g_n[sc], d0 = g_d0[sc];
    float nsq = g_nsq[sc];
    int wrep = (cls < 7) ? (7 + cls) : ((cls == 7) ? 0 : 223);
    int st = g_wst[wrep], cnt = g_wcnt[wrep];

    for (int k = tid; k < n; k += 256) skern[k] = g_kern[sc * KSTR + k];
    if (tid < 40) swt[tid] = g_wt[wrep * 40 + tid];
    __syncthreads();

    int len = n + cnt - 1;
    if (cls < 7) {
        int A = d0 + st - 128;
        int m = sc * 7 + cls;
        int p0 = A - U0;
        float* dst = g_eh + (size_t)m * KE;
        for (int v = tid; v < KE; v += 256) {
            int p = v - p0;
            float acc = 0.0f;
            if (p >= 0 && p < len) {
                int t0 = p - (n - 1); if (t0 < 0) t0 = 0;
                int t1 = p; if (t1 > cnt - 1) t1 = cnt - 1;
                for (int t = t0; t <= t1; t++) acc += swt[t] * skern[p - t];
                acc *= nsq;
            }
            dst[v] = acc;
        }
    } else {
        int sh = (d0 + st) & 3;
        float* dst = g_eke + (size_t)(sc * 2 + (cls - 7)) * EKE;
        for (int v = tid; v < EKE; v += 256) {
            int p = v - sh;
            float acc = 0.0f;
            if (p >= 0 && p < len) {
                int t0 = p - (n - 1); if (t0 < 0) t0 = 0;
                int t1 = p; if (t1 > cnt - 1) t1 = cnt - 1;
                for (int t = t0; t <= t1; t++) acc += swt[t] * skern[p - t];
                acc *= nsq;
            }
            dst[v] = acc;
        }
    }
}

// ---------------- transpose g_eh [m][k] -> g_ehT [k][m] ----------------
__global__ __launch_bounds__(256) void k_trans() {
    __shared__ float t[32][33];
    int k0 = blockIdx.x * 32;
    int m0 = blockIdx.y * 32;
    int tx = threadIdx.x & 31;
    int ty = threadIdx.x >> 5;       // 0..7
    #pragma unroll
    for (int r = 0; r < 4; r++) {
        int m = m0 + ty + r * 8;
        t[ty + r * 8][tx] = g_eh[(size_t)m * KE + k0 + tx];
    }
    __syncthreads();
    #pragma unroll
    for (int r = 0; r < 4; r++) {
        int k = k0 + ty + r * 8;
        g_ehT[(size_t)k * MTOT + m0 + tx] = t[tx][ty + r * 8];
    }
}

// ---------------- main GEMM (split-K, partials) ----------------
__global__ __launch_bounds__(128, 4) void k_gemm() {
    int chunk = blockIdx.y;
    if (chunk >= g_nchk) return;
    int mt  = g_chk[chunk * 2 + 0];
    int klo = g_chk[chunk * 2 + 1];
    int nk  = g_chklen[chunk] >> 4;

    __shared__ float sA[2][BK][SAST];
    __shared__ float sB[2][BK][SBST];

    int nt = blockIdx.x;
    int m0 = mt * BM, n0 = nt * BN;
    int tid = threadIdx.x;
    int warp = tid >> 5, lane = tid & 31;
    int wm = warp >> 1, wn = warp & 1;
    int lm = lane >> 2, ln = lane & 3;
    int m8 = wm * 64 + lm * 8;
    int n8 = wn * 32 + ln * 8;

    int mq = tid & 31, kA = tid >> 5;
    int nb = tid & 63, kh = tid >> 6;
    int ng = n0 + nb; int brow = ng >> 5, bj = ng & 31;

    const float* pA = g_ehT + (size_t)(klo + kA) * MTOT + m0 + mq * 4;
    const float* pB = g_dx + (size_t)brow * DXSTR + U0 + klo + (bj << 7) + kh * 8;

    float4 Ar0, Ar1, Ar2, Ar3, Br0, Br1;
    Ar0 = *(const float4*)(pA);
    Ar1 = *(const float4*)(pA + (size_t)4 * MTOT);
    Ar2 = *(const float4*)(pA + (size_t)8 * MTOT);
    Ar3 = *(const float4*)(pA + (size_t)12 * MTOT);
    Br0 = *(const float4*)(pB);
    Br1 = *(const float4*)(pB + 4);
    {
        *(float4*)&sA[0][kA][mq * 4]      = Ar0;
        *(float4*)&sA[0][kA + 4][mq * 4]  = Ar1;
        *(float4*)&sA[0][kA + 8][mq * 4]  = Ar2;
        *(float4*)&sA[0][kA + 12][mq * 4] = Ar3;
        int k0 = kh * 8;
        sB[0][k0 + 0][nb] = Br0.x; sB[0][k0 + 1][nb] = Br0.y;
        sB[0][k0 + 2][nb] = Br0.z; sB[0][k0 + 3][nb] = Br0.w;
        sB[0][k0 + 4][nb] = Br1.x; sB[0][k0 + 5][nb] = Br1.y;
        sB[0][k0 + 6][nb] = Br1.z; sB[0][k0 + 7][nb] = Br1.w;
    }
    __syncthreads();

    float acc[8][8];
    #pragma unroll
    for (int i = 0; i < 8; i++)
        #pragma unroll
        for (int j = 0; j < 8; j++) acc[i][j] = 0.f;

    for (int kb = 0; kb < nk; kb++) {
        int cur = kb & 1;
        if (kb + 1 < nk) {
            const float* qA = pA + (size_t)(kb + 1) * BK * MTOT;
            const float* qB = pB + (kb + 1) * BK;
            Ar0 = *(const float4*)(qA);
            Ar1 = *(const float4*)(qA + (size_t)4 * MTOT);
            Ar2 = *(const float4*)(qA + (size_t)8 * MTOT);
            Ar3 = *(const float4*)(qA + (size_t)12 * MTOT);
            Br0 = *(const float4*)(qB);
            Br1 = *(const float4*)(qB + 4);
        }
        #pragma unroll
        for (int k = 0; k < BK; k++) {
            float a[8], b[8];
            *(float4*)(a)     = *(const float4*)&sA[cur][k][m8];
            *(float4*)(a + 4) = *(const float4*)&sA[cur][k][m8 + 4];
            *(float4*)(b)     = *(const float4*)&sB[cur][k][n8];
            *(float4*)(b + 4) = *(const float4*)&sB[cur][k][n8 + 4];
            #pragma unroll
            for (int i = 0; i < 8; i++)
                #pragma unroll
                for (int j = 0; j < 8; j++)
                    acc[i][j] = fmaf(a[i], b[j], acc[i][j]);
        }
        if (kb + 1 < nk) {
            int nx = cur ^ 1;
            *(float4*)&sA[nx][kA][mq * 4]      = Ar0;
            *(float4*)&sA[nx][kA + 4][mq * 4]  = Ar1;
            *(float4*)&sA[nx][kA + 8][mq * 4]  = Ar2;
            *(float4*)&sA[nx][kA + 12][mq * 4] = Ar3;
            int k0 = kh * 8;
            sB[nx][k0 + 0][nb] = Br0.x; sB[nx][k0 + 1][nb] = Br0.y;
            sB[nx][k0 + 2][nb] = Br0.z; sB[nx][k0 + 3][nb] = Br0.w;
            sB[nx][k0 + 4][nb] = Br1.x; sB[nx][k0 + 5][nb] = Br1.y;
            sB[nx][k0 + 6][nb] = Br1.z; sB[nx][k0 + 7][nb] = Br1.w;
        }
        __syncthreads();
    }

    float* pp = g_part + ((size_t)chunk * BM) * NTOTAL;
    #pragma unroll
    for (int i = 0; i < 8; i++) {
        float* row = pp + (size_t)(m8 + i) * NTOTAL + n0 + n8;
        float4 v0 = make_float4(acc[i][0], acc[i][1], acc[i][2], acc[i][3]);
        float4 v1 = make_float4(acc[i][4], acc[i][5], acc[i][6], acc[i][7]);
        *(float4*)(row)     = v0;
        *(float4*)(row + 4) = v1;
    }
}

// ---------------- split-K reduction (fully coalesced, m-major out) ----------------
__global__ __launch_bounds__(256) void k_red() {
    int idx = blockIdx.x * 256 + threadIdx.x;
    if (idx >= MTOT * (NTOTAL / 4)) return;
    int m = idx / (NTOTAL / 4);
    int q = idx - m * (NTOTAL / 4);
    int n = q * 4;
    int mt = m >> 7, ml = m & 127;
    int first = g_tfirst[mt], cnt = g_tcnt[mt];
    float4 s = make_float4(0.f, 0.f, 0.f, 0.f);
    for (int c = 0; c < cnt; c++) {
        const float4 v = *(const float4*)(g_part + ((size_t)(first + c) * BM + ml) * NTOTAL + n);
        s.x += v.x; s.y += v.y; s.z += v.z; s.w += v.w;
    }
    *(float4*)(g_tmpB + (size_t)m * NTOTAL + n) = s;
}

// ---------------- permute tmpB [m=(sc,cc)][row*32+jj] -> tmpA [sc][row][w=7jj+cc] ----------------
__global__ __launch_bounds__(224) void k_tr2() {
    __shared__ float sm[224];
    int sc  = blockIdx.x;
    int row = blockIdx.y;
    int t = threadIdx.x;
    int cc = t >> 5, jj = t & 31;
    sm[cc * 32 + jj] = g_tmpB[(size_t)(sc * 7 + cc) * NTOTAL + row * 32 + jj];
    __syncthreads();
    int w = t;
    int j2 = w / 7, c2 = w - j2 * 7;
    g_tmpA[(sc * NROW + row) * OUTW + w] = sm[c2 * 32 + j2];
}

// ---------------- exact fixup for clipped edge columns w=0, w=223 ----------------
__global__ void k_fixup() {
    __shared__ float se[EKE];
    int e  = blockIdx.x;
    int sc = blockIdx.y;
    int tid = threadIdx.x;
    int wE = e ? 223 : 0;
    int n = g_n[sc], d0 = g_d0[sc];
    int st = g_wst[wE], cnt = g_wcnt[wE];
    int base = (d0 + st) & ~3;
    int sh = (d0 + st) & 3;
    int qmax = sh + n + cnt - 1;

    const float* esrc = g_eke + (size_t)(sc * 2 + e) * EKE;
    for (int i = tid * 4; i < EKE; i += 1024)
        *(float4*)(se + i) = *(const float4*)(esrc + i);
    __syncthreads();

    int wi = tid >> 5, lane = tid & 31;
    for (int row = wi; row < NROW; row += 8) {
        const float* dxr = g_dx + (size_t)row * DXSTR + base;
        float p = 0.f;
        for (int q = lane * 4; q < qmax; q += 128) {
            float4 d = *(const float4*)(dxr + q);
            float4 ev = *(const float4*)(se + q);
            p = fmaf(d.x, ev.x, fmaf(d.y, ev.y, fmaf(d.z, ev.z, fmaf(d.w, ev.w, p))));
        }
        #pragma unroll
        for (int o = 16; o > 0; o >>= 1) p += __shfl_xor_sync(0xffffffffu, p, o);
        if (lane == 0) g_tmpA[(sc * NROW + row) * OUTW + wE] = p;
    }
}

// ---------------- resize stage B: scale axis 128 -> 224 ----------------
__global__ void k_resize_h(float* __restrict__ out) {
    int idx = blockIdx.x * blockDim.x + threadIdx.x;
    if (idx >= OUTN) return;
    int c = idx % Cn;
    int w = (idx / Cn) % OUTW;
    int h = (idx / (Cn * OUTW)) % OUTH;
    int b = idx / (Cn * OUTW * OUTH);
    int i0 = g_whi[h * 2 + 0], i1 = g_whi[h * 2 + 1];
    float f0 = g_whw[h * 2 + 0], f1 = g_whw[h * 2 + 1];
    int rb = (c * Bn + b) * OUTW + w;
    out[idx] = f0 * g_tmpA[i0 * NROW * OUTW + rb] + f1 * g_tmpA[i1 * NROW * OUTW + rb];
}

// ---------------- launch ----------------
extern "C" void kernel_launch(void* const* d_in, const int* in_sizes, int n_in,
                              void* d_out, int out_size) {
    const float* x   = (const float*)d_in[0];       // (32, 4096, 3) f32
    const float* psi = (const float*)d_in[1];       // (4096,) f32
    float* out = (float*)d_out;

    k_setup<<<1, 256>>>();
    k_gather<<<NSC, 256>>>(psi);
    k_dx<<<(NROW * DXSTR + 255) / 256, 256>>>(x);
    k_ebuild<<<dim3(9, NSC), 256>>>();               // profile slot 3
    k_trans<<<dim3(KE / 32, MTOT / 32), 256>>>();
    k_gemm<<<dim3(48, MAXCH), 128>>>();
    k_red<<<(MTOT * (NTOTAL / 4) + 255) / 256, 256>>>();
    k_tr2<<<dim3(NSC, NROW), 224>>>();
    k_fixup<<<dim3(2, NSC), 256>>>();
    k_resize_h<<<(OUTN + 255) / 256, 256>>>(out);
}